// round 1
// baseline (speedup 1.0000x reference)
#include <cuda_runtime.h>

#define NPTS  16384
#define BATCH 16
#define HID   512
#define EMB   64
#define TSTEPS 8
#define OUTC  218

// ---- scratch (static device allocations; no cudaMalloc allowed) ----
__device__ float g_u[NPTS * HID];            // 32 MB: point_embeds @ hm_w1[:512]
__device__ float g_vt[TSTEPS * HID];         // traj_emb @ hm_w1[512:] + b1
__device__ float g_logits[NPTS * TSTEPS];
__device__ float g_newc[NPTS * TSTEPS * 3];
__device__ float g_pc[BATCH * HID];          // segment max-pool of point_embeds

// ============================================================================
// K1: u = A(16384x512) @ B(512x512).  Classic 128x128 tile SGEMM, 256 thr,
//     8x8 microtile, BK=8, float4 smem traffic.
// ============================================================================
__global__ __launch_bounds__(256, 2) void k1_gemm(const float* __restrict__ A,
                                                  const float* __restrict__ B) {
    __shared__ float As[8][128];
    __shared__ float Bs[8][128];
    const int tid = threadIdx.x;
    const int bm = blockIdx.x, bn = blockIdx.y;
    const int tx = tid & 15, ty = tid >> 4;

    float acc[8][8];
#pragma unroll
    for (int i = 0; i < 8; i++)
#pragma unroll
        for (int j = 0; j < 8; j++) acc[i][j] = 0.f;

    const float* Ab = A + (size_t)bm * 128 * HID;
    const int arow = tid >> 1, akq = tid & 1;       // A: 128 rows x 2 float4
    const int bk = tid >> 5, bcq = tid & 31;        // B: 8 k x 32 float4

    for (int kt = 0; kt < HID; kt += 8) {
        float4 av = *(const float4*)(Ab + arow * HID + kt + akq * 4);
        As[akq * 4 + 0][arow] = av.x;
        As[akq * 4 + 1][arow] = av.y;
        As[akq * 4 + 2][arow] = av.z;
        As[akq * 4 + 3][arow] = av.w;
        float4 bv = *(const float4*)(B + (size_t)(kt + bk) * HID + bn * 128 + bcq * 4);
        *(float4*)&Bs[bk][bcq * 4] = bv;
        __syncthreads();

#pragma unroll
        for (int k = 0; k < 8; k++) {
            float4 a0 = *(const float4*)&As[k][ty * 8];
            float4 a1 = *(const float4*)&As[k][ty * 8 + 4];
            float4 b0 = *(const float4*)&Bs[k][tx * 8];
            float4 b1 = *(const float4*)&Bs[k][tx * 8 + 4];
            float a[8] = {a0.x, a0.y, a0.z, a0.w, a1.x, a1.y, a1.z, a1.w};
            float b[8] = {b0.x, b0.y, b0.z, b0.w, b1.x, b1.y, b1.z, b1.w};
#pragma unroll
            for (int i = 0; i < 8; i++)
#pragma unroll
                for (int j = 0; j < 8; j++) acc[i][j] += a[i] * b[j];
        }
        __syncthreads();
    }

#pragma unroll
    for (int i = 0; i < 8; i++) {
        float* crow = g_u + (size_t)(bm * 128 + ty * 8 + i) * HID + bn * 128 + tx * 8;
        float4 v0 = {acc[i][0], acc[i][1], acc[i][2], acc[i][3]};
        float4 v1 = {acc[i][4], acc[i][5], acc[i][6], acc[i][7]};
        *(float4*)crow = v0;
        *(float4*)(crow + 4) = v1;
    }
}

// ============================================================================
// K2: vt[t][j] = hm_b1[j] + sum_e traj[t][e] * hm_w1[512+e][j]
// ============================================================================
__global__ void k2_vt(const float* __restrict__ traj, const float* __restrict__ w1,
                      const float* __restrict__ b1) {
    int t = blockIdx.x, j = threadIdx.x;
    float acc = b1[j];
#pragma unroll 8
    for (int e = 0; e < EMB; e++) acc += traj[t * EMB + e] * w1[(size_t)(HID + e) * HID + j];
    g_vt[t * HID + j] = acc;
}

// ============================================================================
// K3: per point n, per t: h = lrelu(u[n] + vt[t]);
//     logits[n][t] = h . w2[:,0] + b2[0];  newc = coords + h . w2[:,1:4] + b2[1:4]
//     One block (128 thr) per point; u row in registers; vt + w2^T in smem.
// ============================================================================
__global__ __launch_bounds__(128) void k3_hm(const float* __restrict__ coords,
                                             const float* __restrict__ w2,
                                             const float* __restrict__ b2) {
    __shared__ float vts[TSTEPS * HID];     // 16 KB
    __shared__ float w2s[4][HID];           // transposed: 8 KB
    __shared__ float wsum[4][4];            // [warp][c]
    const int n = blockIdx.x, tid = threadIdx.x;
    const int lane = tid & 31, warp = tid >> 5;

    for (int i = tid; i < TSTEPS * HID; i += 128) vts[i] = g_vt[i];
    for (int i = tid; i < HID * 4; i += 128) w2s[i & 3][i >> 2] = w2[i];

    float ur[4];
#pragma unroll
    for (int q = 0; q < 4; q++) ur[q] = g_u[(size_t)n * HID + q * 128 + tid];
    __syncthreads();

    for (int t = 0; t < TSTEPS; t++) {
        float a0 = 0.f, a1 = 0.f, a2 = 0.f, a3 = 0.f;
#pragma unroll
        for (int q = 0; q < 4; q++) {
            int j = q * 128 + tid;
            float h = ur[q] + vts[t * HID + j];
            h = h >= 0.f ? h : 0.02f * h;
            a0 += h * w2s[0][j];
            a1 += h * w2s[1][j];
            a2 += h * w2s[2][j];
            a3 += h * w2s[3][j];
        }
#pragma unroll
        for (int o = 16; o > 0; o >>= 1) {
            a0 += __shfl_down_sync(0xffffffffu, a0, o);
            a1 += __shfl_down_sync(0xffffffffu, a1, o);
            a2 += __shfl_down_sync(0xffffffffu, a2, o);
            a3 += __shfl_down_sync(0xffffffffu, a3, o);
        }
        if (lane == 0) {
            wsum[warp][0] = a0; wsum[warp][1] = a1;
            wsum[warp][2] = a2; wsum[warp][3] = a3;
        }
        __syncthreads();
        if (tid < 4) {
            float f = wsum[0][tid] + wsum[1][tid] + wsum[2][tid] + wsum[3][tid] + b2[tid];
            if (tid == 0) g_logits[n * TSTEPS + t] = f;
            else g_newc[(n * TSTEPS + t) * 3 + (tid - 1)] = coords[n * 3 + (tid - 1)] + f;
        }
        __syncthreads();
    }
}

// ============================================================================
// K4: per segment b: stable softmax over points (per t) and weighted sum of
//     new coords -> xt (written straight to out[0:384]).
// ============================================================================
__global__ __launch_bounds__(256) void k4_soft(const int* __restrict__ np,
                                               float* __restrict__ out) {
    const int b = blockIdx.x, tid = threadIdx.x;
    const int lane = tid & 31, warp = tid >> 5;
    int start = 0;
    for (int i = 0; i < b; i++) start += np[i];
    const int end = start + np[b];

    // phase A: max per t
    float lm[TSTEPS];
#pragma unroll
    for (int t = 0; t < TSTEPS; t++) lm[t] = -1e30f;
    for (int p = start + tid; p < end; p += 256) {
#pragma unroll
        for (int t = 0; t < TSTEPS; t++) lm[t] = fmaxf(lm[t], g_logits[p * TSTEPS + t]);
    }
    __shared__ float smax[TSTEPS][8];
    __shared__ float m8[TSTEPS];
#pragma unroll
    for (int t = 0; t < TSTEPS; t++) {
        float v = lm[t];
#pragma unroll
        for (int o = 16; o > 0; o >>= 1) v = fmaxf(v, __shfl_down_sync(0xffffffffu, v, o));
        if (lane == 0) smax[t][warp] = v;
    }
    __syncthreads();
    if (tid < TSTEPS) {
        float v = -1e30f;
        for (int w = 0; w < 8; w++) v = fmaxf(v, smax[tid][w]);
        m8[tid] = v;
    }
    __syncthreads();

    // phase B: sum e, sum e*newc
    float s[TSTEPS], sc[TSTEPS][3];
#pragma unroll
    for (int t = 0; t < TSTEPS; t++) { s[t] = 0.f; sc[t][0] = sc[t][1] = sc[t][2] = 0.f; }
    for (int p = start + tid; p < end; p += 256) {
#pragma unroll
        for (int t = 0; t < TSTEPS; t++) {
            float e = expf(g_logits[p * TSTEPS + t] - m8[t]);
            s[t] += e;
            const float* nc = g_newc + (size_t)(p * TSTEPS + t) * 3;
            sc[t][0] += e * nc[0];
            sc[t][1] += e * nc[1];
            sc[t][2] += e * nc[2];
        }
    }
    __shared__ float sred[8][32];
    __shared__ float fin[32];
#pragma unroll
    for (int t = 0; t < TSTEPS; t++) {
#pragma unroll
        for (int c = 0; c < 4; c++) {
            float v = (c == 0) ? s[t] : sc[t][c - 1];
#pragma unroll
            for (int o = 16; o > 0; o >>= 1) v += __shfl_down_sync(0xffffffffu, v, o);
            if (lane == 0) sred[warp][t * 4 + c] = v;
        }
    }
    __syncthreads();
    if (tid < 32) {
        float tot = 0.f;
        for (int w = 0; w < 8; w++) tot += sred[w][tid];
        fin[tid] = tot;
    }
    __syncthreads();
    if (tid < TSTEPS) {
        float inv = 1.f / fin[tid * 4];
        for (int c = 0; c < 3; c++)
            out[(b * TSTEPS + tid) * 3 + c] = fin[tid * 4 + 1 + c] * inv;
    }
}

// ============================================================================
// K5: segment max-pool of point_embeds -> g_pc (B,512)
//     grid (B,4), block (128,8): 128 cols x 8 row-groups, smem reduce.
// ============================================================================
__global__ __launch_bounds__(1024) void k5_pool(const float* __restrict__ pe,
                                                const int* __restrict__ np) {
    __shared__ float sm[8][128];
    const int b = blockIdx.x;
    const int col = blockIdx.y * 128 + threadIdx.x;
    const int ty = threadIdx.y;
    int start = 0;
    for (int i = 0; i < b; i++) start += np[i];
    const int end = start + np[b];

    float m0 = -1e30f, m1 = -1e30f, m2 = -1e30f, m3 = -1e30f;
    int p = start + ty;
    for (; p + 24 < end; p += 32) {
        m0 = fmaxf(m0, pe[(size_t)p * HID + col]);
        m1 = fmaxf(m1, pe[(size_t)(p + 8) * HID + col]);
        m2 = fmaxf(m2, pe[(size_t)(p + 16) * HID + col]);
        m3 = fmaxf(m3, pe[(size_t)(p + 24) * HID + col]);
    }
    for (; p < end; p += 8) m0 = fmaxf(m0, pe[(size_t)p * HID + col]);
    float m = fmaxf(fmaxf(m0, m1), fmaxf(m2, m3));
    sm[ty][threadIdx.x] = m;
    __syncthreads();
    if (ty == 0) {
        for (int w = 1; w < 8; w++) m = fmaxf(m, sm[w][threadIdx.x]);
        g_pc[b * HID + col] = m;
    }
}

// ============================================================================
// K6: act MLP per (b,t): row = [pc[b], traj[t]];
//     hid = lrelu(row @ act_w1 + b1); ae = hid @ act_w2 + b2; scatter outputs.
// ============================================================================
__global__ __launch_bounds__(256) void k6_act(const float* __restrict__ traj,
                                              const float* __restrict__ w1,
                                              const float* __restrict__ b1,
                                              const float* __restrict__ w2,
                                              const float* __restrict__ b2,
                                              float* __restrict__ out) {
    __shared__ float row[HID + EMB];
    __shared__ float hid[HID];
    const int bt = blockIdx.x;
    const int b = bt >> 3, t = bt & 7;
    const int tid = threadIdx.x;

    for (int i = tid; i < HID; i += 256) row[i] = g_pc[b * HID + i];
    if (tid < EMB) row[HID + tid] = traj[t * EMB + tid];
    __syncthreads();

#pragma unroll
    for (int jj = 0; jj < 2; jj++) {
        int j = jj * 256 + tid;
        float acc = b1[j];
#pragma unroll 4
        for (int k = 0; k < HID + EMB; k++) acc += row[k] * w1[(size_t)k * HID + j];
        hid[j] = acc >= 0.f ? acc : 0.02f * acc;
    }
    __syncthreads();

    if (tid < OUTC) {
        float acc = b2[tid];
#pragma unroll 4
        for (int k = 0; k < HID; k++) acc += hid[k] * w2[(size_t)k * OUTC + tid];
        const int XT = BATCH * TSTEPS * 3;                 // 384
        const int XR = BATCH * TSTEPS * 216;               // 27648
        if (tid < 216)       out[XT + bt * 216 + tid] = acc;
        else if (tid == 216) out[XT + XR + bt] = acc;
        else                 out[XT + XR + BATCH * TSTEPS + bt] = acc;
    }
}

// ============================================================================
extern "C" void kernel_launch(void* const* d_in, const int* in_sizes, int n_in,
                              void* d_out, int out_size) {
    const float* pe     = (const float*)d_in[0];
    const float* coords = (const float*)d_in[1];
    const float* traj   = (const float*)d_in[2];
    const float* hw1    = (const float*)d_in[3];
    const float* hb1    = (const float*)d_in[4];
    const float* hw2    = (const float*)d_in[5];
    const float* hb2    = (const float*)d_in[6];
    const float* aw1    = (const float*)d_in[7];
    const float* ab1    = (const float*)d_in[8];
    const float* aw2    = (const float*)d_in[9];
    const float* ab2    = (const float*)d_in[10];
    const int*   np     = (const int*)d_in[11];
    float* out = (float*)d_out;

    k1_gemm<<<dim3(NPTS / 128, HID / 128), 256>>>(pe, hw1);
    k2_vt<<<TSTEPS, HID>>>(traj, hw1, hb1);
    k3_hm<<<NPTS, 128>>>(coords, hw2, hb2);
    k4_soft<<<BATCH, 256>>>(np, out);
    k5_pool<<<dim3(BATCH, HID / 128), dim3(128, 8)>>>(pe, np);
    k6_act<<<BATCH * TSTEPS, 256>>>(traj, aw1, ab1, aw2, ab2, out);
}

// round 3
// speedup vs baseline: 1.3601x; 1.3601x over previous
#include <cuda_runtime.h>
#include <cuda_bf16.h>
#include <cstdint>

#define NPTS   16384
#define BATCH  16
#define HID    512
#define EMB    64
#define TSTEPS 8
#define OUTC   218
#define NSTEP  48            // K = 1536 in 32-wide k-steps

// ---- scratch (static device allocations) ----
__device__ __align__(128) __nv_bfloat16 g_A2[NPTS * 1024];   // [ah | al] per row
__device__ __align__(128) __nv_bfloat16 g_Wc[HID * 1024];    // [wh | wl] per n-row, K contig
__device__ float g_u[NPTS * HID];
__device__ float g_vt[TSTEPS * HID];
__device__ float g_logits[NPTS * TSTEPS];
__device__ float g_newc[NPTS * TSTEPS * 3];
__device__ float g_pc[BATCH * HID];

// ============================ PTX helpers ====================================
__device__ __forceinline__ uint32_t smem_u32(const void* p) {
    uint32_t a;
    asm("{ .reg .u64 t; cvta.to.shared.u64 t, %1; cvt.u32.u64 %0, t; }" : "=r"(a) : "l"(p));
    return a;
}
#define CP_ASYNC16(dst, src) \
    asm volatile("cp.async.cg.shared.global [%0], [%1], 16;" :: "r"(dst), "l"(src) : "memory")
#define CP_COMMIT() asm volatile("cp.async.commit_group;" ::: "memory")
#define CP_WAIT(n)  asm volatile("cp.async.wait_group %0;" :: "n"(n) : "memory")

#define LDSM4(d, a) \
    asm volatile("ldmatrix.sync.aligned.m8n8.x4.shared.b16 {%0,%1,%2,%3}, [%4];" \
                 : "=r"((d)[0]), "=r"((d)[1]), "=r"((d)[2]), "=r"((d)[3]) : "r"(a))

#define MMA_BF16(c, a, b) \
    asm volatile( \
        "mma.sync.aligned.m16n8k16.row.col.f32.bf16.bf16.f32 " \
        "{%0,%1,%2,%3},{%4,%5,%6,%7},{%8,%9},{%0,%1,%2,%3};" \
        : "+f"((c)[0]), "+f"((c)[1]), "+f"((c)[2]), "+f"((c)[3]) \
        : "r"((a)[0]), "r"((a)[1]), "r"((a)[2]), "r"((a)[3]), "r"((b)[0]), "r"((b)[1]))

// ============================================================================
// K0a: split point_embeds fp32 -> bf16 hi/lo into g_A2 [16384][1024]
// ============================================================================
__global__ __launch_bounds__(256) void k0a_conv(const float* __restrict__ pe) {
    int idx = blockIdx.x * 256 + threadIdx.x;
    int row = idx >> 6, g = idx & 63;
    const float* src = pe + (size_t)row * HID + g * 8;
    float4 f0 = *(const float4*)src;
    float4 f1 = *(const float4*)(src + 4);
    float f[8] = {f0.x, f0.y, f0.z, f0.w, f1.x, f1.y, f1.z, f1.w};
    __align__(16) __nv_bfloat16 hi[8], lo[8];
#pragma unroll
    for (int i = 0; i < 8; i++) {
        hi[i] = __float2bfloat16(f[i]);
        lo[i] = __float2bfloat16(f[i] - __bfloat162float(hi[i]));
    }
    __nv_bfloat16* dst = g_A2 + (size_t)row * 1024 + g * 8;
    *(uint4*)dst = *(const uint4*)hi;
    *(uint4*)(dst + 512) = *(const uint4*)lo;
}

// ============================================================================
// K0w: transpose + split hm_w1[:512] -> g_Wc [512 n][1024 k] (hi|lo)
// ============================================================================
__global__ __launch_bounds__(256) void k0w_conv(const float* __restrict__ w1) {
    int n = blockIdx.x;
    for (int k = threadIdx.x; k < 1024; k += 256) {
        int kk = k & 511, s = k >> 9;
        float f = w1[(size_t)kk * HID + n];
        __nv_bfloat16 hi = __float2bfloat16(f);
        g_Wc[(size_t)n * 1024 + k] = s ? __float2bfloat16(f - __bfloat162float(hi)) : hi;
    }
}

// ============================================================================
// K2: vt[t][j] = hm_b1[j] + traj[t] . hm_w1[512:][:,j]   (fp32, exact-ish)
// ============================================================================
__global__ void k2_vt(const float* __restrict__ traj, const float* __restrict__ w1,
                      const float* __restrict__ b1) {
    int t = blockIdx.x, j = threadIdx.x;
    float acc = b1[j];
#pragma unroll 8
    for (int e = 0; e < EMB; e++) acc += traj[t * EMB + e] * w1[(size_t)(HID + e) * HID + j];
    g_vt[t * HID + j] = acc;
}

// ============================================================================
// KGEMM: u(16384x512) = A_cat(16384x1536 bf16) @ W_cat(1536x512 bf16)
//   split terms: [ah|al|ah] x [wh|wh|wl].  mma.sync m16n8k16, CTA 128x128,
//   4-stage cp.async, tile-major smem (8x8 tiles contiguous, conflict-free).
// smem: A stages [4][8192] @0, B stages [4][8192] @32768  => 64 KB dynamic
// ============================================================================
__global__ __launch_bounds__(256, 1) void kgemm() {
    extern __shared__ char smem[];
    const uint32_t sb = smem_u32(smem);
    const int tid = threadIdx.x;
    const int lane = tid & 31, w = tid >> 5;
    const int wm = w >> 1, wn = w & 1;          // warp grid 4(m) x 2(n)
    const int bm = blockIdx.x, bn = blockIdx.y;
    const int ti = lane >> 3, r = lane & 7;

    float acc[2][8][4];
#pragma unroll
    for (int i = 0; i < 2; i++)
#pragma unroll
        for (int j = 0; j < 8; j++)
#pragma unroll
            for (int q = 0; q < 4; q++) acc[i][j][q] = 0.f;

    const char* Ab = (const char*)g_A2 + (size_t)bm * 128 * 2048;
    const char* Bb = (const char*)g_Wc + (size_t)bn * 128 * 2048;

    auto stage_load = [&](int s) {
        const int buf = s & 3;
        const int aof = (s < 16) ? s * 32 : (s < 32) ? 512 + (s - 16) * 32 : (s - 32) * 32;
        const int bof = (s < 32) ? (s & 15) * 32 : 512 + (s - 32) * 32;
        const uint32_t dA = sb + buf * 8192;
        const uint32_t dB = sb + 32768 + buf * 8192;
#pragma unroll
        for (int h = 0; h < 2; h++) {
            int q = h * 256 + tid;
            int m = q >> 2, kg = q & 3;
            uint32_t off = (uint32_t)(((((m >> 3) * 4) + kg) * 8 + (m & 7)) * 16);
            CP_ASYNC16(dA + off, Ab + (size_t)m * 2048 + (size_t)(aof + kg * 8) * 2);
            CP_ASYNC16(dB + off, Bb + (size_t)m * 2048 + (size_t)(bof + kg * 8) * 2);
        }
        CP_COMMIT();
    };

    stage_load(0); stage_load(1); stage_load(2);

    for (int s = 0; s < NSTEP; s++) {
        CP_WAIT(2);
        __syncthreads();
        const uint32_t sA = sb + (s & 3) * 8192;
        const uint32_t sB = sb + 32768 + (s & 3) * 8192;
#pragma unroll
        for (int kk = 0; kk < 2; kk++) {
            uint32_t af[2][4];
#pragma unroll
            for (int i = 0; i < 2; i++) {
                uint32_t addr = sA + (uint32_t)((((((wm * 2 + i) * 2 + (ti & 1)) * 4) +
                                                 (kk * 2 + (ti >> 1))) * 8 + r) * 16);
                LDSM4(af[i], addr);
            }
            uint32_t bf[4][4];
#pragma unroll
            for (int j = 0; j < 4; j++) {
                uint32_t addr = sB + (uint32_t)((((((wn * 4 + j) * 2 + (ti >> 1)) * 4) +
                                                 (kk * 2 + (ti & 1))) * 8 + r) * 16);
                LDSM4(bf[j], addr);
            }
#pragma unroll
            for (int i = 0; i < 2; i++)
#pragma unroll
                for (int j = 0; j < 8; j++)
                    MMA_BF16(acc[i][j], af[i], &bf[j >> 1][(j & 1) * 2]);
        }
        if (s + 3 < NSTEP) stage_load(s + 3); else CP_COMMIT();
    }

    // epilogue: write u tile
#pragma unroll
    for (int i = 0; i < 2; i++) {
        int m0 = bm * 128 + (wm * 2 + i) * 16 + (lane >> 2);
#pragma unroll
        for (int j = 0; j < 8; j++) {
            int n0 = bn * 128 + wn * 64 + j * 8 + (lane & 3) * 2;
            *(float2*)&g_u[(size_t)m0 * HID + n0] = make_float2(acc[i][j][0], acc[i][j][1]);
            *(float2*)&g_u[(size_t)(m0 + 8) * HID + n0] = make_float2(acc[i][j][2], acc[i][j][3]);
        }
    }
}

// ============================================================================
// K3b: heatmap head.  128 blocks x 128 thr, 1 point/thread, u staged via smem.
//   logits[p][t] = lrelu(u[p]+vt[t]) . w2[:,0] + b2[0]
//   newc[p][t][c] = coords[p][c] + lrelu(u[p]+vt[t]) . w2[:,1+c] + b2[1+c]
// ============================================================================
__global__ __launch_bounds__(128) void k3b(const float* __restrict__ coords,
                                           const float* __restrict__ w2,
                                           const float* __restrict__ b2) {
    __shared__ float vtT[HID * 8];     // [j][t]
    __shared__ float w2s[HID * 4];     // [j][c]
    __shared__ float su[128 * 33];     // u chunk, stride 33 (conflict-free)
    const int tid = threadIdx.x;
    const int p = blockIdx.x * 128 + tid;

    for (int i = tid; i < TSTEPS * HID; i += 128) {
        int t = i >> 9, j = i & 511;
        vtT[j * 8 + t] = g_vt[i];
    }
    for (int i = tid; i < HID * 4; i += 128) w2s[i] = w2[i];

    float acc[32];
#pragma unroll
    for (int i = 0; i < 32; i++) acc[i] = 0.f;

    const float* ub = g_u + (size_t)blockIdx.x * 128 * HID;
    for (int jc = 0; jc < 16; jc++) {
        __syncthreads();
#pragma unroll
        for (int h = 0; h < 8; h++) {
            int q = h * 128 + tid;           // float4 index 0..1023
            int row = q >> 3, c4 = q & 7;
            float4 v = *(const float4*)(ub + (size_t)row * HID + jc * 32 + c4 * 4);
            float* d = su + row * 33 + c4 * 4;
            d[0] = v.x; d[1] = v.y; d[2] = v.z; d[3] = v.w;
        }
        __syncthreads();
        const float* myrow = su + tid * 33;
#pragma unroll
        for (int j = 0; j < 32; j++) {
            float u = myrow[j];
            int jg = jc * 32 + j;
            const float* vt8 = vtT + jg * 8;
            float4 wv = *(const float4*)(w2s + jg * 4);
#pragma unroll
            for (int t = 0; t < 8; t++) {
                float x = u + vt8[t];
                float h = fmaxf(x, 0.02f * x);
                acc[t * 4 + 0] += h * wv.x;
                acc[t * 4 + 1] += h * wv.y;
                acc[t * 4 + 2] += h * wv.z;
                acc[t * 4 + 3] += h * wv.w;
            }
        }
    }

    const float b2v[4] = {b2[0], b2[1], b2[2], b2[3]};
    const float c3[3] = {coords[p * 3], coords[p * 3 + 1], coords[p * 3 + 2]};
#pragma unroll
    for (int t = 0; t < 8; t++) {
        g_logits[p * 8 + t] = acc[t * 4] + b2v[0];
#pragma unroll
        for (int c = 0; c < 3; c++)
            g_newc[(p * 8 + t) * 3 + c] = c3[c] + acc[t * 4 + 1 + c] + b2v[1 + c];
    }
}

// ============================================================================
// K4: per (segment, t): stable softmax + weighted coord sum -> out[0:384]
// ============================================================================
__global__ __launch_bounds__(256) void k4_soft(const int* __restrict__ np,
                                               float* __restrict__ out) {
    const int b = blockIdx.x >> 3, t = blockIdx.x & 7;
    const int tid = threadIdx.x, lane = tid & 31, warp = tid >> 5;
    int start = 0;
    for (int i = 0; i < b; i++) start += np[i];
    const int end = start + np[b];

    __shared__ float sred[8][4];
    __shared__ float mshared;

    float m = -1e30f;
    for (int p = start + tid; p < end; p += 256) m = fmaxf(m, g_logits[p * 8 + t]);
#pragma unroll
    for (int o = 16; o > 0; o >>= 1) m = fmaxf(m, __shfl_down_sync(0xffffffffu, m, o));
    if (lane == 0) sred[warp][0] = m;
    __syncthreads();
    if (tid == 0) {
        float v = sred[0][0];
        for (int i = 1; i < 8; i++) v = fmaxf(v, sred[i][0]);
        mshared = v;
    }
    __syncthreads();
    const float mx = mshared;

    float s = 0.f, sx = 0.f, sy = 0.f, sz = 0.f;
    for (int p = start + tid; p < end; p += 256) {
        float e = expf(g_logits[p * 8 + t] - mx);
        const float* nc = g_newc + (size_t)(p * 8 + t) * 3;
        s += e; sx += e * nc[0]; sy += e * nc[1]; sz += e * nc[2];
    }
#pragma unroll
    for (int o = 16; o > 0; o >>= 1) {
        s  += __shfl_down_sync(0xffffffffu, s,  o);
        sx += __shfl_down_sync(0xffffffffu, sx, o);
        sy += __shfl_down_sync(0xffffffffu, sy, o);
        sz += __shfl_down_sync(0xffffffffu, sz, o);
    }
    if (lane == 0) { sred[warp][0] = s; sred[warp][1] = sx; sred[warp][2] = sy; sred[warp][3] = sz; }
    __syncthreads();
    if (tid == 0) {
        float ts = 0, tx = 0, ty = 0, tz = 0;
        for (int i = 0; i < 8; i++) { ts += sred[i][0]; tx += sred[i][1]; ty += sred[i][2]; tz += sred[i][3]; }
        float inv = 1.f / ts;
        out[(b * 8 + t) * 3 + 0] = tx * inv;
        out[(b * 8 + t) * 3 + 1] = ty * inv;
        out[(b * 8 + t) * 3 + 2] = tz * inv;
    }
}

// ============================================================================
// K5: segment max-pool of point_embeds -> g_pc
// ============================================================================
__global__ __launch_bounds__(1024) void k5_pool(const float* __restrict__ pe,
                                                const int* __restrict__ np) {
    __shared__ float sm[8][128];
    const int b = blockIdx.x;
    const int col = blockIdx.y * 128 + threadIdx.x;
    const int ty = threadIdx.y;
    int start = 0;
    for (int i = 0; i < b; i++) start += np[i];
    const int end = start + np[b];

    float m0 = -1e30f, m1 = -1e30f, m2 = -1e30f, m3 = -1e30f;
    int p = start + ty;
    for (; p + 24 < end; p += 32) {
        m0 = fmaxf(m0, pe[(size_t)p * HID + col]);
        m1 = fmaxf(m1, pe[(size_t)(p + 8) * HID + col]);
        m2 = fmaxf(m2, pe[(size_t)(p + 16) * HID + col]);
        m3 = fmaxf(m3, pe[(size_t)(p + 24) * HID + col]);
    }
    for (; p < end; p += 8) m0 = fmaxf(m0, pe[(size_t)p * HID + col]);
    float m = fmaxf(fmaxf(m0, m1), fmaxf(m2, m3));
    sm[ty][threadIdx.x] = m;
    __syncthreads();
    if (ty == 0) {
        for (int w = 1; w < 8; w++) m = fmaxf(m, sm[w][threadIdx.x]);
        g_pc[b * HID + col] = m;
    }
}

// ============================================================================
// K6: act MLP per (b,t)
// ============================================================================
__global__ __launch_bounds__(256) void k6_act(const float* __restrict__ traj,
                                              const float* __restrict__ w1,
                                              const float* __restrict__ b1,
                                              const float* __restrict__ w2,
                                              const float* __restrict__ b2,
                                              float* __restrict__ out) {
    __shared__ float row[HID + EMB];
    __shared__ float hid[HID];
    const int bt = blockIdx.x;
    const int b = bt >> 3, t = bt & 7;
    const int tid = threadIdx.x;

    for (int i = tid; i < HID; i += 256) row[i] = g_pc[b * HID + i];
    if (tid < EMB) row[HID + tid] = traj[t * EMB + tid];
    __syncthreads();

#pragma unroll
    for (int jj = 0; jj < 2; jj++) {
        int j = jj * 256 + tid;
        float acc = b1[j];
#pragma unroll 4
        for (int k = 0; k < HID + EMB; k++) acc += row[k] * w1[(size_t)k * HID + j];
        hid[j] = acc >= 0.f ? acc : 0.02f * acc;
    }
    __syncthreads();

    if (tid < OUTC) {
        float acc = b2[tid];
#pragma unroll 4
        for (int k = 0; k < HID; k++) acc += hid[k] * w2[(size_t)k * OUTC + tid];
        const int XT = BATCH * TSTEPS * 3;
        const int XR = BATCH * TSTEPS * 216;
        if (tid < 216)       out[XT + bt * 216 + tid] = acc;
        else if (tid == 216) out[XT + XR + bt] = acc;
        else                 out[XT + XR + BATCH * TSTEPS + bt] = acc;
    }
}

// ============================================================================
extern "C" void kernel_launch(void* const* d_in, const int* in_sizes, int n_in,
                              void* d_out, int out_size) {
    const float* pe     = (const float*)d_in[0];
    const float* coords = (const float*)d_in[1];
    const float* traj   = (const float*)d_in[2];
    const float* hw1    = (const float*)d_in[3];
    const float* hb1    = (const float*)d_in[4];
    const float* hw2    = (const float*)d_in[5];
    const float* hb2    = (const float*)d_in[6];
    const float* aw1    = (const float*)d_in[7];
    const float* ab1    = (const float*)d_in[8];
    const float* aw2    = (const float*)d_in[9];
    const float* ab2    = (const float*)d_in[10];
    const int*   np     = (const int*)d_in[11];
    float* out = (float*)d_out;

    static bool attr_set = false;
    if (!attr_set) {
        cudaFuncSetAttribute(kgemm, cudaFuncAttributeMaxDynamicSharedMemorySize, 65536);
        attr_set = true;
    }

    k0a_conv<<<NPTS * 64 / 256, 256>>>(pe);
    k0w_conv<<<HID, 256>>>(hw1);
    k2_vt<<<TSTEPS, HID>>>(traj, hw1, hb1);
    kgemm<<<dim3(NPTS / 128, HID / 128), 256, 65536>>>();
    k3b<<<NPTS / 128, 128>>>(coords, hw2, hb2);
    k4_soft<<<BATCH * TSTEPS, 256>>>(np, out);
    k5_pool<<<dim3(BATCH, HID / 128), dim3(128, 8)>>>(pe, np);
    k6_act<<<BATCH * TSTEPS, 256>>>(traj, aw1, ab1, aw2, ab2, out);
}

// round 4
// speedup vs baseline: 1.3908x; 1.0226x over previous
#include <cuda_runtime.h>
#include <cuda_bf16.h>
#include <cstdint>

#define NPTS   16384
#define BATCH  16
#define HID    512
#define EMB    64
#define TSTEPS 8
#define OUTC   218
#define NSTEP  48            // K = 1536 in 32-wide k-steps

// ---- scratch (static device allocations) ----
__device__ __align__(128) __nv_bfloat16 g_A2[NPTS * 1024];   // [ah | al] per row
__device__ __align__(128) __nv_bfloat16 g_Wc[HID * 1024];    // [wh | wl] per n-row, K contig
__device__ float g_u[NPTS * HID];
__device__ float g_vt[TSTEPS * HID];
__device__ float g_logits[NPTS * TSTEPS];
__device__ float g_newc[NPTS * TSTEPS * 3];
__device__ float g_pp[BATCH * 8 * HID];
__device__ float g_pc[BATCH * HID];

// ============================ PTX helpers ====================================
__device__ __forceinline__ uint32_t smem_u32(const void* p) {
    uint32_t a;
    asm("{ .reg .u64 t; cvta.to.shared.u64 t, %1; cvt.u32.u64 %0, t; }" : "=r"(a) : "l"(p));
    return a;
}
#define CP_ASYNC16(dst, src) \
    asm volatile("cp.async.cg.shared.global [%0], [%1], 16;" :: "r"(dst), "l"(src) : "memory")
#define CP_COMMIT() asm volatile("cp.async.commit_group;" ::: "memory")
#define CP_WAIT(n)  asm volatile("cp.async.wait_group %0;" :: "n"(n) : "memory")

#define LDSM4(d, a) \
    asm volatile("ldmatrix.sync.aligned.m8n8.x4.shared.b16 {%0,%1,%2,%3}, [%4];" \
                 : "=r"((d)[0]), "=r"((d)[1]), "=r"((d)[2]), "=r"((d)[3]) : "r"(a))

#define MMA_BF16(c, a, b) \
    asm volatile( \
        "mma.sync.aligned.m16n8k16.row.col.f32.bf16.bf16.f32 " \
        "{%0,%1,%2,%3},{%4,%5,%6,%7},{%8,%9},{%0,%1,%2,%3};" \
        : "+f"((c)[0]), "+f"((c)[1]), "+f"((c)[2]), "+f"((c)[3]) \
        : "r"((a)[0]), "r"((a)[1]), "r"((a)[2]), "r"((a)[3]), "r"((b)[0]), "r"((b)[1]))

// ============================================================================
// K0a: split point_embeds fp32 -> bf16 hi/lo into g_A2 [16384][1024]
// ============================================================================
__global__ __launch_bounds__(256) void k0a_conv(const float* __restrict__ pe) {
    int idx = blockIdx.x * 256 + threadIdx.x;
    int row = idx >> 6, g = idx & 63;
    const float* src = pe + (size_t)row * HID + g * 8;
    float4 f0 = *(const float4*)src;
    float4 f1 = *(const float4*)(src + 4);
    float f[8] = {f0.x, f0.y, f0.z, f0.w, f1.x, f1.y, f1.z, f1.w};
    __align__(16) __nv_bfloat16 hi[8], lo[8];
#pragma unroll
    for (int i = 0; i < 8; i++) {
        hi[i] = __float2bfloat16(f[i]);
        lo[i] = __float2bfloat16(f[i] - __bfloat162float(hi[i]));
    }
    __nv_bfloat16* dst = g_A2 + (size_t)row * 1024 + g * 8;
    *(uint4*)dst = *(const uint4*)hi;
    *(uint4*)(dst + 512) = *(const uint4*)lo;
}

// ============================================================================
// K0w: coalesced transpose + split hm_w1[:512] -> g_Wc [512 n][1024 k]
//   grid (16,16), block (32,8), 32x32 tiles via smem
// ============================================================================
__global__ void k0w_conv(const float* __restrict__ w1) {
    __shared__ float s[32][33];
    const int tx = threadIdx.x, ty = threadIdx.y;
    const int kb = blockIdx.y * 32, nb = blockIdx.x * 32;
#pragma unroll
    for (int i = 0; i < 4; i++) {
        int k = ty + i * 8;
        s[k][tx] = w1[(size_t)(kb + k) * HID + nb + tx];
    }
    __syncthreads();
#pragma unroll
    for (int i = 0; i < 4; i++) {
        int nr = ty + i * 8;
        float f = s[tx][nr];
        __nv_bfloat16 hi = __float2bfloat16(f);
        __nv_bfloat16 lo = __float2bfloat16(f - __bfloat162float(hi));
        g_Wc[(size_t)(nb + nr) * 1024 + kb + tx] = hi;
        g_Wc[(size_t)(nb + nr) * 1024 + 512 + kb + tx] = lo;
    }
}

// ============================================================================
// K2: vt[t][j] = hm_b1[j] + traj[t] . hm_w1[512:][:,j]
// ============================================================================
__global__ void k2_vt(const float* __restrict__ traj, const float* __restrict__ w1,
                      const float* __restrict__ b1) {
    int t = blockIdx.x, j = threadIdx.x;
    float acc = b1[j];
#pragma unroll 8
    for (int e = 0; e < EMB; e++) acc += traj[t * EMB + e] * w1[(size_t)(HID + e) * HID + j];
    g_vt[t * HID + j] = acc;
}

// ============================================================================
// KGEMM v2: u = A_cat @ W_cat.  CTA 256m x 128n, 512 thr (16 warps 4x4),
//   warp tile 64x32, 4-stage cp.async K=32, tile-major smem (8x8 = 128B).
// smem: A 4x16KB @0, B 4x8KB @65536 -> 96KB
// ============================================================================
__global__ __launch_bounds__(512) void kgemm() {
    extern __shared__ char smem[];
    const uint32_t sb = smem_u32(smem);
    const int tid = threadIdx.x;
    const int lane = tid & 31, w = tid >> 5;
    const int wm = w >> 2, wn = w & 3;          // warp grid 4(m) x 4(n)
    const int bm = blockIdx.x, bn = blockIdx.y;
    const int ti = lane >> 3, r = lane & 7;

    float acc[4][4][4];
#pragma unroll
    for (int i = 0; i < 4; i++)
#pragma unroll
        for (int j = 0; j < 4; j++)
#pragma unroll
            for (int q = 0; q < 4; q++) acc[i][j][q] = 0.f;

    const char* Ab = (const char*)g_A2 + (size_t)bm * 256 * 2048;
    const char* Bb = (const char*)g_Wc + (size_t)bn * 128 * 2048;

    auto stage_load = [&](int s) {
        const int buf = s & 3;
        const int aof = (s < 16) ? s * 32 : (s < 32) ? 512 + (s - 16) * 32 : (s - 32) * 32;
        const int bof = (s < 32) ? (s & 15) * 32 : 512 + (s - 32) * 32;
        const uint32_t dA = sb + buf * 16384;
        const uint32_t dB = sb + 65536 + buf * 8192;
#pragma unroll
        for (int h = 0; h < 2; h++) {
            int q = h * 512 + tid;
            int m = q >> 2, kg = q & 3;
            uint32_t off = (uint32_t)((((m >> 3) * 4 + kg) * 8 + (m & 7)) * 16);
            CP_ASYNC16(dA + off, Ab + (size_t)m * 2048 + (size_t)(aof + kg * 8) * 2);
        }
        {
            int n = tid >> 2, kg = tid & 3;
            uint32_t off = (uint32_t)((((n >> 3) * 4 + kg) * 8 + (n & 7)) * 16);
            CP_ASYNC16(dB + off, Bb + (size_t)n * 2048 + (size_t)(bof + kg * 8) * 2);
        }
        CP_COMMIT();
    };

    stage_load(0); stage_load(1); stage_load(2);

    for (int s = 0; s < NSTEP; s++) {
        CP_WAIT(2);
        __syncthreads();
        const uint32_t sA = sb + (s & 3) * 16384;
        const uint32_t sB = sb + 65536 + (s & 3) * 8192;
#pragma unroll
        for (int kk = 0; kk < 2; kk++) {
            uint32_t af[4][4];
#pragma unroll
            for (int i = 0; i < 4; i++) {
                int m8 = (wm * 4 + i) * 2 + (ti & 1);
                int k8 = kk * 2 + (ti >> 1);
                LDSM4(af[i], sA + (uint32_t)(((m8 * 4 + k8) * 8 + r) * 16));
            }
            uint32_t bf[2][4];
#pragma unroll
            for (int pj = 0; pj < 2; pj++) {
                int n8 = wn * 4 + pj * 2 + (ti >> 1);
                int k8 = kk * 2 + (ti & 1);
                LDSM4(bf[pj], sB + (uint32_t)(((n8 * 4 + k8) * 8 + r) * 16));
            }
#pragma unroll
            for (int i = 0; i < 4; i++)
#pragma unroll
                for (int j = 0; j < 4; j++)
                    MMA_BF16(acc[i][j], af[i], &bf[j >> 1][(j & 1) * 2]);
        }
        if (s + 3 < NSTEP) stage_load(s + 3); else CP_COMMIT();
    }

    // epilogue: write u tile
#pragma unroll
    for (int i = 0; i < 4; i++) {
        int m0 = bm * 256 + wm * 64 + i * 16 + (lane >> 2);
#pragma unroll
        for (int j = 0; j < 4; j++) {
            int n0 = bn * 128 + wn * 32 + j * 8 + (lane & 3) * 2;
            *(float2*)&g_u[(size_t)m0 * HID + n0] = make_float2(acc[i][j][0], acc[i][j][1]);
            *(float2*)&g_u[(size_t)(m0 + 8) * HID + n0] = make_float2(acc[i][j][2], acc[i][j][3]);
        }
    }
}

// ============================================================================
// K3b v2: heatmap head.  128 blocks x 256 thr; 2 threads/point (j-halves).
//   dynamic smem: vtT 16KB | w2s 8KB | su[128][65] 33.3KB = 57856 B
// ============================================================================
#define K3_SMEM 57856
__global__ __launch_bounds__(256) void k3b(const float* __restrict__ coords,
                                           const float* __restrict__ w2,
                                           const float* __restrict__ b2) {
    extern __shared__ float sm3[];
    float* vtT = sm3;              // [j][t]  4096
    float* w2s = sm3 + 4096;       // [j][c]  2048
    float* su  = sm3 + 6144;       // [128][65]
    const int tid = threadIdx.x;
    const int half = tid >> 7, pi = tid & 127;
    const int p = blockIdx.x * 128 + pi;

    for (int i = tid; i < TSTEPS * HID; i += 256) {
        int t = i >> 9, j = i & 511;
        vtT[j * 8 + t] = g_vt[i];
    }
    for (int i = tid; i < HID * 4; i += 256) w2s[i] = w2[i];

    float acc[32];
#pragma unroll
    for (int i = 0; i < 32; i++) acc[i] = 0.f;

    const float* ub = g_u + (size_t)blockIdx.x * 128 * HID;
    for (int jc = 0; jc < 8; jc++) {
        __syncthreads();
#pragma unroll
        for (int h = 0; h < 8; h++) {
            int q = h * 256 + tid;              // 2048 float4 slots
            int row = q >> 4, c4 = q & 15;
            int jsrc = (c4 < 8) ? jc * 32 + c4 * 4 : 256 + jc * 32 + (c4 - 8) * 4;
            float4 v = *(const float4*)(ub + (size_t)row * HID + jsrc);
            float* d = su + row * 65 + c4 * 4;
            d[0] = v.x; d[1] = v.y; d[2] = v.z; d[3] = v.w;
        }
        __syncthreads();
        const float* myrow = su + pi * 65 + half * 32;
#pragma unroll
        for (int j = 0; j < 32; j++) {
            float u = myrow[j];
            int jg = half * 256 + jc * 32 + j;
            const float* vt8 = vtT + jg * 8;
            float4 wv = *(const float4*)(w2s + jg * 4);
#pragma unroll
            for (int t = 0; t < 8; t++) {
                float x = u + vt8[t];
                float h = fmaxf(x, 0.02f * x);
                acc[t * 4 + 0] += h * wv.x;
                acc[t * 4 + 1] += h * wv.y;
                acc[t * 4 + 2] += h * wv.z;
                acc[t * 4 + 3] += h * wv.w;
            }
        }
    }

    __syncthreads();
    if (half == 1) {
        float* d = su + pi * 65;
#pragma unroll
        for (int i = 0; i < 32; i++) d[i] = acc[i];
    }
    __syncthreads();
    if (half == 0) {
        const float* q = su + pi * 65;
        const float b2v[4] = {b2[0], b2[1], b2[2], b2[3]};
        const float c3[3] = {coords[p * 3], coords[p * 3 + 1], coords[p * 3 + 2]};
#pragma unroll
        for (int t = 0; t < 8; t++) {
            g_logits[p * 8 + t] = acc[t * 4] + q[t * 4] + b2v[0];
#pragma unroll
            for (int c = 0; c < 3; c++)
                g_newc[(p * 8 + t) * 3 + c] =
                    c3[c] + acc[t * 4 + 1 + c] + q[t * 4 + 1 + c] + b2v[1 + c];
        }
    }
}

// ============================================================================
// K4: per (segment, t): stable softmax + weighted coord sum -> out[0:384]
// ============================================================================
__global__ __launch_bounds__(256) void k4_soft(const int* __restrict__ np,
                                               float* __restrict__ out) {
    const int b = blockIdx.x >> 3, t = blockIdx.x & 7;
    const int tid = threadIdx.x, lane = tid & 31, warp = tid >> 5;
    int start = 0;
    for (int i = 0; i < b; i++) start += np[i];
    const int end = start + np[b];

    __shared__ float sred[8][4];
    __shared__ float mshared;

    float m = -1e30f;
    for (int p = start + tid; p < end; p += 256) m = fmaxf(m, g_logits[p * 8 + t]);
#pragma unroll
    for (int o = 16; o > 0; o >>= 1) m = fmaxf(m, __shfl_down_sync(0xffffffffu, m, o));
    if (lane == 0) sred[warp][0] = m;
    __syncthreads();
    if (tid == 0) {
        float v = sred[0][0];
        for (int i = 1; i < 8; i++) v = fmaxf(v, sred[i][0]);
        mshared = v;
    }
    __syncthreads();
    const float mx = mshared;

    float s = 0.f, sx = 0.f, sy = 0.f, sz = 0.f;
    for (int p = start + tid; p < end; p += 256) {
        float e = expf(g_logits[p * 8 + t] - mx);
        const float* nc = g_newc + (size_t)(p * 8 + t) * 3;
        s += e; sx += e * nc[0]; sy += e * nc[1]; sz += e * nc[2];
    }
#pragma unroll
    for (int o = 16; o > 0; o >>= 1) {
        s  += __shfl_down_sync(0xffffffffu, s,  o);
        sx += __shfl_down_sync(0xffffffffu, sx, o);
        sy += __shfl_down_sync(0xffffffffu, sy, o);
        sz += __shfl_down_sync(0xffffffffu, sz, o);
    }
    if (lane == 0) { sred[warp][0] = s; sred[warp][1] = sx; sred[warp][2] = sy; sred[warp][3] = sz; }
    __syncthreads();
    if (tid == 0) {
        float ts = 0, tx = 0, ty = 0, tz = 0;
        for (int i = 0; i < 8; i++) { ts += sred[i][0]; tx += sred[i][1]; ty += sred[i][2]; tz += sred[i][3]; }
        float inv = 1.f / ts;
        out[(b * 8 + t) * 3 + 0] = tx * inv;
        out[(b * 8 + t) * 3 + 1] = ty * inv;
        out[(b * 8 + t) * 3 + 2] = tz * inv;
    }
}

// ============================================================================
// K5a/b: segment max-pool of point_embeds, two-phase
// ============================================================================
__global__ __launch_bounds__(128) void k5a(const float* __restrict__ pe,
                                           const int* __restrict__ np) {
    const int b = blockIdx.x;
    const int col = blockIdx.y * 128 + threadIdx.x;
    const int chunk = blockIdx.z;
    int start = 0;
    for (int i = 0; i < b; i++) start += np[i];
    const int len = np[b];
    const int c0 = start + (chunk * len) / 8;
    const int c1 = start + ((chunk + 1) * len) / 8;

    float m0 = -1e30f, m1 = -1e30f, m2 = -1e30f, m3 = -1e30f;
    int p = c0;
    for (; p + 3 < c1; p += 4) {
        m0 = fmaxf(m0, pe[(size_t)p * HID + col]);
        m1 = fmaxf(m1, pe[(size_t)(p + 1) * HID + col]);
        m2 = fmaxf(m2, pe[(size_t)(p + 2) * HID + col]);
        m3 = fmaxf(m3, pe[(size_t)(p + 3) * HID + col]);
    }
    for (; p < c1; p++) m0 = fmaxf(m0, pe[(size_t)p * HID + col]);
    g_pp[(b * 8 + chunk) * HID + col] = fmaxf(fmaxf(m0, m1), fmaxf(m2, m3));
}

__global__ __launch_bounds__(128) void k5b() {
    const int b = blockIdx.x;
    const int col = blockIdx.y * 128 + threadIdx.x;
    float m = -1e30f;
#pragma unroll
    for (int c = 0; c < 8; c++) m = fmaxf(m, g_pp[(b * 8 + c) * HID + col]);
    g_pc[b * HID + col] = m;
}

// ============================================================================
// K6: act MLP per (b,t)
// ============================================================================
__global__ __launch_bounds__(256) void k6_act(const float* __restrict__ traj,
                                              const float* __restrict__ w1,
                                              const float* __restrict__ b1,
                                              const float* __restrict__ w2,
                                              const float* __restrict__ b2,
                                              float* __restrict__ out) {
    __shared__ float row[HID + EMB];
    __shared__ float hid[HID];
    const int bt = blockIdx.x;
    const int b = bt >> 3, t = bt & 7;
    const int tid = threadIdx.x;

    for (int i = tid; i < HID; i += 256) row[i] = g_pc[b * HID + i];
    if (tid < EMB) row[HID + tid] = traj[t * EMB + tid];
    __syncthreads();

#pragma unroll
    for (int jj = 0; jj < 2; jj++) {
        int j = jj * 256 + tid;
        float acc = b1[j];
#pragma unroll 4
        for (int k = 0; k < HID + EMB; k++) acc += row[k] * w1[(size_t)k * HID + j];
        hid[j] = acc >= 0.f ? acc : 0.02f * acc;
    }
    __syncthreads();

    if (tid < OUTC) {
        float acc = b2[tid];
#pragma unroll 4
        for (int k = 0; k < HID; k++) acc += hid[k] * w2[(size_t)k * OUTC + tid];
        const int XT = BATCH * TSTEPS * 3;
        const int XR = BATCH * TSTEPS * 216;
        if (tid < 216)       out[XT + bt * 216 + tid] = acc;
        else if (tid == 216) out[XT + XR + bt] = acc;
        else                 out[XT + XR + BATCH * TSTEPS + bt] = acc;
    }
}

// ============================================================================
extern "C" void kernel_launch(void* const* d_in, const int* in_sizes, int n_in,
                              void* d_out, int out_size) {
    const float* pe     = (const float*)d_in[0];
    const float* coords = (const float*)d_in[1];
    const float* traj   = (const float*)d_in[2];
    const float* hw1    = (const float*)d_in[3];
    const float* hb1    = (const float*)d_in[4];
    const float* hw2    = (const float*)d_in[5];
    const float* hb2    = (const float*)d_in[6];
    const float* aw1    = (const float*)d_in[7];
    const float* ab1    = (const float*)d_in[8];
    const float* aw2    = (const float*)d_in[9];
    const float* ab2    = (const float*)d_in[10];
    const int*   np     = (const int*)d_in[11];
    float* out = (float*)d_out;

    static bool attr_set = false;
    if (!attr_set) {
        cudaFuncSetAttribute(kgemm, cudaFuncAttributeMaxDynamicSharedMemorySize, 98304);
        cudaFuncSetAttribute(k3b, cudaFuncAttributeMaxDynamicSharedMemorySize, K3_SMEM);
        attr_set = true;
    }

    k0a_conv<<<NPTS * 64 / 256, 256>>>(pe);
    k0w_conv<<<dim3(16, 16), dim3(32, 8)>>>(hw1);
    k2_vt<<<TSTEPS, HID>>>(traj, hw1, hb1);
    kgemm<<<dim3(NPTS / 256, HID / 128), 512, 98304>>>();
    k3b<<<NPTS / 128, 256, K3_SMEM>>>(coords, hw2, hb2);
    k4_soft<<<BATCH * TSTEPS, 256>>>(np, out);
    k5a<<<dim3(BATCH, HID / 128, 8), 128>>>(pe, np);
    k5b<<<dim3(BATCH, HID / 128), 128>>>();
    k6_act<<<BATCH * TSTEPS, 256>>>(traj, aw1, ab1, aw2, ab2, out);
}

// round 5
// speedup vs baseline: 1.4113x; 1.0147x over previous
#include <cuda_runtime.h>
#include <cuda_bf16.h>
#include <cstdint>

#define NPTS   16384
#define BATCH  16
#define HID    512
#define EMB    64
#define TSTEPS 8
#define OUTC   218
#define NSTEP  48            // K = 1536 in 32-wide k-steps

// ---- scratch (static device allocations) ----
__device__ __align__(128) __nv_bfloat16 g_A2[NPTS * 1024];   // [ah | al] per row
__device__ __align__(128) __nv_bfloat16 g_Wc[HID * 1024];    // [wh | wl] per n-row, K contig
__device__ float g_u[NPTS * HID];
__device__ float g_logits[NPTS * TSTEPS];
__device__ float g_newc[NPTS * TSTEPS * 3];
__device__ float g_pp[BATCH * 8 * HID];

// ============================ PTX helpers ====================================
__device__ __forceinline__ uint32_t smem_u32(const void* p) {
    uint32_t a;
    asm("{ .reg .u64 t; cvta.to.shared.u64 t, %1; cvt.u32.u64 %0, t; }" : "=r"(a) : "l"(p));
    return a;
}
#define CP_ASYNC16(dst, src) \
    asm volatile("cp.async.cg.shared.global [%0], [%1], 16;" :: "r"(dst), "l"(src) : "memory")
#define CP_COMMIT() asm volatile("cp.async.commit_group;" ::: "memory")
#define CP_WAIT(n)  asm volatile("cp.async.wait_group %0;" :: "n"(n) : "memory")

#define LDSM4(d, a) \
    asm volatile("ldmatrix.sync.aligned.m8n8.x4.shared.b16 {%0,%1,%2,%3}, [%4];" \
                 : "=r"((d)[0]), "=r"((d)[1]), "=r"((d)[2]), "=r"((d)[3]) : "r"(a))

#define MMA_BF16(c, a, b) \
    asm volatile( \
        "mma.sync.aligned.m16n8k16.row.col.f32.bf16.bf16.f32 " \
        "{%0,%1,%2,%3},{%4,%5,%6,%7},{%8,%9},{%0,%1,%2,%3};" \
        : "+f"((c)[0]), "+f"((c)[1]), "+f"((c)[2]), "+f"((c)[3]) \
        : "r"((a)[0]), "r"((a)[1]), "r"((a)[2]), "r"((a)[3]), "r"((b)[0]), "r"((b)[1]))

// ============================================================================
// K0a: split point_embeds fp32 -> bf16 hi/lo into g_A2 [16384][1024]
// ============================================================================
__global__ __launch_bounds__(256) void k0a_conv(const float* __restrict__ pe) {
    int idx = blockIdx.x * 256 + threadIdx.x;
    int row = idx >> 6, g = idx & 63;
    const float* src = pe + (size_t)row * HID + g * 8;
    float4 f0 = *(const float4*)src;
    float4 f1 = *(const float4*)(src + 4);
    float f[8] = {f0.x, f0.y, f0.z, f0.w, f1.x, f1.y, f1.z, f1.w};
    __align__(16) __nv_bfloat16 hi[8], lo[8];
#pragma unroll
    for (int i = 0; i < 8; i++) {
        hi[i] = __float2bfloat16(f[i]);
        lo[i] = __float2bfloat16(f[i] - __bfloat162float(hi[i]));
    }
    __nv_bfloat16* dst = g_A2 + (size_t)row * 1024 + g * 8;
    *(uint4*)dst = *(const uint4*)hi;
    *(uint4*)(dst + 512) = *(const uint4*)lo;
}

// ============================================================================
// K0w: coalesced transpose + split hm_w1[:512] -> g_Wc [512 n][1024 k]
// ============================================================================
__global__ void k0w_conv(const float* __restrict__ w1) {
    __shared__ float s[32][33];
    const int tx = threadIdx.x, ty = threadIdx.y;
    const int kb = blockIdx.y * 32, nb = blockIdx.x * 32;
#pragma unroll
    for (int i = 0; i < 4; i++) {
        int k = ty + i * 8;
        s[k][tx] = w1[(size_t)(kb + k) * HID + nb + tx];
    }
    __syncthreads();
#pragma unroll
    for (int i = 0; i < 4; i++) {
        int nr = ty + i * 8;
        float f = s[tx][nr];
        __nv_bfloat16 hi = __float2bfloat16(f);
        __nv_bfloat16 lo = __float2bfloat16(f - __bfloat162float(hi));
        g_Wc[(size_t)(nb + nr) * 1024 + kb + tx] = hi;
        g_Wc[(size_t)(nb + nr) * 1024 + 512 + kb + tx] = lo;
    }
}

// ============================================================================
// KGEMM v3: u = A_cat @ W_cat.  CTA 256m x 128n, 256 thr (8 warps 4x2),
//   warp tile 64x64 (64 indep MMAs/warp/kk), 4-stage cp.async K=32.
// smem: A 4x16KB @0, B 4x8KB @65536 -> 96KB
// ============================================================================
__global__ __launch_bounds__(256) void kgemm() {
    extern __shared__ char smem[];
    const uint32_t sb = smem_u32(smem);
    const int tid = threadIdx.x;
    const int lane = tid & 31, w = tid >> 5;
    const int wm = w >> 1, wn = w & 1;          // warp grid 4(m) x 2(n)
    const int bm = blockIdx.x, bn = blockIdx.y;
    const int ti = lane >> 3, r = lane & 7;

    float acc[4][8][4];
#pragma unroll
    for (int i = 0; i < 4; i++)
#pragma unroll
        for (int j = 0; j < 8; j++)
#pragma unroll
            for (int q = 0; q < 4; q++) acc[i][j][q] = 0.f;

    const char* Ab = (const char*)g_A2 + (size_t)bm * 256 * 2048;
    const char* Bb = (const char*)g_Wc + (size_t)bn * 128 * 2048;

    auto stage_load = [&](int s) {
        const int buf = s & 3;
        const int aof = (s < 16) ? s * 32 : (s < 32) ? 512 + (s - 16) * 32 : (s - 32) * 32;
        const int bof = (s < 32) ? (s & 15) * 32 : 512 + (s - 32) * 32;
        const uint32_t dA = sb + buf * 16384;
        const uint32_t dB = sb + 65536 + buf * 8192;
#pragma unroll
        for (int h = 0; h < 4; h++) {
            int q = h * 256 + tid;
            int m = q >> 2, kg = q & 3;
            uint32_t off = (uint32_t)((((m >> 3) * 4 + kg) * 8 + (m & 7)) * 16);
            CP_ASYNC16(dA + off, Ab + (size_t)m * 2048 + (size_t)(aof + kg * 8) * 2);
        }
#pragma unroll
        for (int h = 0; h < 2; h++) {
            int q = h * 256 + tid;
            int n = q >> 2, kg = q & 3;
            uint32_t off = (uint32_t)((((n >> 3) * 4 + kg) * 8 + (n & 7)) * 16);
            CP_ASYNC16(dB + off, Bb + (size_t)n * 2048 + (size_t)(bof + kg * 8) * 2);
        }
        CP_COMMIT();
    };

    stage_load(0); stage_load(1); stage_load(2);

    for (int s = 0; s < NSTEP; s++) {
        CP_WAIT(2);
        __syncthreads();
        const uint32_t sA = sb + (s & 3) * 16384;
        const uint32_t sB = sb + 65536 + (s & 3) * 8192;
#pragma unroll
        for (int kk = 0; kk < 2; kk++) {
            uint32_t af[4][4];
#pragma unroll
            for (int i = 0; i < 4; i++) {
                int m8 = (wm * 4 + i) * 2 + (ti & 1);
                int k8 = kk * 2 + (ti >> 1);
                LDSM4(af[i], sA + (uint32_t)(((m8 * 4 + k8) * 8 + r) * 16));
            }
            uint32_t bf[4][4];
#pragma unroll
            for (int pj = 0; pj < 4; pj++) {
                int n8 = wn * 8 + pj * 2 + (ti >> 1);
                int k8 = kk * 2 + (ti & 1);
                LDSM4(bf[pj], sB + (uint32_t)(((n8 * 4 + k8) * 8 + r) * 16));
            }
#pragma unroll
            for (int i = 0; i < 4; i++)
#pragma unroll
                for (int j = 0; j < 8; j++)
                    MMA_BF16(acc[i][j], af[i], &bf[j >> 1][(j & 1) * 2]);
        }
        if (s + 3 < NSTEP) stage_load(s + 3); else CP_COMMIT();
    }

    // epilogue: write u tile
#pragma unroll
    for (int i = 0; i < 4; i++) {
        int m0 = bm * 256 + wm * 64 + i * 16 + (lane >> 2);
#pragma unroll
        for (int j = 0; j < 8; j++) {
            int n0 = bn * 128 + wn * 64 + j * 8 + (lane & 3) * 2;
            *(float2*)&g_u[(size_t)m0 * HID + n0] = make_float2(acc[i][j][0], acc[i][j][1]);
            *(float2*)&g_u[(size_t)(m0 + 8) * HID + n0] = make_float2(acc[i][j][2], acc[i][j][3]);
        }
    }
}

// ============================================================================
// K3b v3 (launch #4 -> gets profiled): heatmap head, vt fused in.
//   128 blocks x 256 thr; 2 threads/point (j-halves), u staged via smem.
//   dynamic smem: vtT 16KB | w2s 8KB | su[128][65] 33.3KB = 57856 B
// ============================================================================
#define K3_SMEM 57856
__global__ __launch_bounds__(256) void k3b(const float* __restrict__ coords,
                                           const float* __restrict__ traj,
                                           const float* __restrict__ w1,
                                           const float* __restrict__ b1,
                                           const float* __restrict__ w2,
                                           const float* __restrict__ b2) {
    extern __shared__ float sm3[];
    float* vtT = sm3;              // [j][t]  4096
    float* w2s = sm3 + 4096;       // [j][c]  2048
    float* su  = sm3 + 6144;       // [128][65]
    const int tid = threadIdx.x;
    const int half = tid >> 7, pi = tid & 127;
    const int p = blockIdx.x * 128 + pi;

    // traj into su (temp), w2 into smem
    for (int i = tid; i < TSTEPS * EMB; i += 256) su[i] = traj[i];
    for (int i = tid; i < HID * 4; i += 256) w2s[i] = w2[i];
    __syncthreads();

    // vt[t][j] = b1[j] + traj[t] . w1[512:][:,j]  (coalesced w1 reads)
#pragma unroll
    for (int jj = 0; jj < 2; jj++) {
        const int j = jj * 256 + tid;
        float a8[8];
#pragma unroll
        for (int t = 0; t < 8; t++) a8[t] = b1[j];
        for (int e = 0; e < EMB; e++) {
            float we = w1[(size_t)(HID + e) * HID + j];
#pragma unroll
            for (int t = 0; t < 8; t++) a8[t] += su[t * EMB + e] * we;
        }
#pragma unroll
        for (int t = 0; t < 8; t++) vtT[j * 8 + t] = a8[t];
    }
    __syncthreads();

    float acc[32];
#pragma unroll
    for (int i = 0; i < 32; i++) acc[i] = 0.f;

    const float* ub = g_u + (size_t)blockIdx.x * 128 * HID;
    for (int jc = 0; jc < 8; jc++) {
        __syncthreads();
#pragma unroll
        for (int h = 0; h < 8; h++) {
            int q = h * 256 + tid;              // 2048 float4 slots
            int row = q >> 4, c4 = q & 15;
            int jsrc = (c4 < 8) ? jc * 32 + c4 * 4 : 256 + jc * 32 + (c4 - 8) * 4;
            float4 v = *(const float4*)(ub + (size_t)row * HID + jsrc);
            float* d = su + row * 65 + c4 * 4;
            d[0] = v.x; d[1] = v.y; d[2] = v.z; d[3] = v.w;
        }
        __syncthreads();
        const float* myrow = su + pi * 65 + half * 32;
#pragma unroll
        for (int j = 0; j < 32; j++) {
            float u = myrow[j];
            int jg = half * 256 + jc * 32 + j;
            const float* vt8 = vtT + jg * 8;
            float4 wv = *(const float4*)(w2s + jg * 4);
#pragma unroll
            for (int t = 0; t < 8; t++) {
                float x = u + vt8[t];
                float h = fmaxf(x, 0.02f * x);
                acc[t * 4 + 0] += h * wv.x;
                acc[t * 4 + 1] += h * wv.y;
                acc[t * 4 + 2] += h * wv.z;
                acc[t * 4 + 3] += h * wv.w;
            }
        }
    }

    __syncthreads();
    if (half == 1) {
        float* d = su + pi * 65;
#pragma unroll
        for (int i = 0; i < 32; i++) d[i] = acc[i];
    }
    __syncthreads();
    if (half == 0) {
        const float* q = su + pi * 65;
        const float b2v[4] = {b2[0], b2[1], b2[2], b2[3]};
        const float c3[3] = {coords[p * 3], coords[p * 3 + 1], coords[p * 3 + 2]};
#pragma unroll
        for (int t = 0; t < 8; t++) {
            g_logits[p * 8 + t] = acc[t * 4] + q[t * 4] + b2v[0];
#pragma unroll
            for (int c = 0; c < 3; c++)
                g_newc[(p * 8 + t) * 3 + c] =
                    c3[c] + acc[t * 4 + 1 + c] + q[t * 4 + 1 + c] + b2v[1 + c];
        }
    }
}

// ============================================================================
// K4: per (segment, t): stable softmax + weighted coord sum -> out[0:384]
// ============================================================================
__global__ __launch_bounds__(256) void k4_soft(const int* __restrict__ np,
                                               float* __restrict__ out) {
    const int b = blockIdx.x >> 3, t = blockIdx.x & 7;
    const int tid = threadIdx.x, lane = tid & 31, warp = tid >> 5;
    int start = 0;
    for (int i = 0; i < b; i++) start += np[i];
    const int end = start + np[b];

    __shared__ float sred[8][4];
    __shared__ float mshared;

    float m = -1e30f;
    for (int p = start + tid; p < end; p += 256) m = fmaxf(m, g_logits[p * 8 + t]);
#pragma unroll
    for (int o = 16; o > 0; o >>= 1) m = fmaxf(m, __shfl_down_sync(0xffffffffu, m, o));
    if (lane == 0) sred[warp][0] = m;
    __syncthreads();
    if (tid == 0) {
        float v = sred[0][0];
        for (int i = 1; i < 8; i++) v = fmaxf(v, sred[i][0]);
        mshared = v;
    }
    __syncthreads();
    const float mx = mshared;

    float s = 0.f, sx = 0.f, sy = 0.f, sz = 0.f;
    for (int p = start + tid; p < end; p += 256) {
        float e = expf(g_logits[p * 8 + t] - mx);
        const float* nc = g_newc + (size_t)(p * 8 + t) * 3;
        s += e; sx += e * nc[0]; sy += e * nc[1]; sz += e * nc[2];
    }
#pragma unroll
    for (int o = 16; o > 0; o >>= 1) {
        s  += __shfl_down_sync(0xffffffffu, s,  o);
        sx += __shfl_down_sync(0xffffffffu, sx, o);
        sy += __shfl_down_sync(0xffffffffu, sy, o);
        sz += __shfl_down_sync(0xffffffffu, sz, o);
    }
    if (lane == 0) { sred[warp][0] = s; sred[warp][1] = sx; sred[warp][2] = sy; sred[warp][3] = sz; }
    __syncthreads();
    if (tid == 0) {
        float ts = 0, tx = 0, ty = 0, tz = 0;
        for (int i = 0; i < 8; i++) { ts += sred[i][0]; tx += sred[i][1]; ty += sred[i][2]; tz += sred[i][3]; }
        float inv = 1.f / ts;
        out[(b * 8 + t) * 3 + 0] = tx * inv;
        out[(b * 8 + t) * 3 + 1] = ty * inv;
        out[(b * 8 + t) * 3 + 2] = tz * inv;
    }
}

// ============================================================================
// K5a: segment max-pool phase 1 -> g_pp [b][chunk][512]
// ============================================================================
__global__ __launch_bounds__(128) void k5a(const float* __restrict__ pe,
                                           const int* __restrict__ np) {
    const int b = blockIdx.x;
    const int col = blockIdx.y * 128 + threadIdx.x;
    const int chunk = blockIdx.z;
    int start = 0;
    for (int i = 0; i < b; i++) start += np[i];
    const int len = np[b];
    const int c0 = start + (chunk * len) / 8;
    const int c1 = start + ((chunk + 1) * len) / 8;

    float m0 = -1e30f, m1 = -1e30f, m2 = -1e30f, m3 = -1e30f;
    int p = c0;
    for (; p + 3 < c1; p += 4) {
        m0 = fmaxf(m0, pe[(size_t)p * HID + col]);
        m1 = fmaxf(m1, pe[(size_t)(p + 1) * HID + col]);
        m2 = fmaxf(m2, pe[(size_t)(p + 2) * HID + col]);
        m3 = fmaxf(m3, pe[(size_t)(p + 3) * HID + col]);
    }
    for (; p < c1; p++) m0 = fmaxf(m0, pe[(size_t)p * HID + col]);
    g_pp[(b * 8 + chunk) * HID + col] = fmaxf(fmaxf(m0, m1), fmaxf(m2, m3));
}

// ============================================================================
// K6: act MLP per (b,t), phase-2 max fused into row load
// ============================================================================
__global__ __launch_bounds__(256) void k6_act(const float* __restrict__ traj,
                                              const float* __restrict__ w1,
                                              const float* __restrict__ b1,
                                              const float* __restrict__ w2,
                                              const float* __restrict__ b2,
                                              float* __restrict__ out) {
    __shared__ float row[HID + EMB];
    __shared__ float hid[HID];
    const int bt = blockIdx.x;
    const int b = bt >> 3, t = bt & 7;
    const int tid = threadIdx.x;

    for (int i = tid; i < HID; i += 256) {
        float m = -1e30f;
#pragma unroll
        for (int c = 0; c < 8; c++) m = fmaxf(m, g_pp[(b * 8 + c) * HID + i]);
        row[i] = m;
    }
    if (tid < EMB) row[HID + tid] = traj[t * EMB + tid];
    __syncthreads();

#pragma unroll
    for (int jj = 0; jj < 2; jj++) {
        int j = jj * 256 + tid;
        float acc = b1[j];
#pragma unroll 4
        for (int k = 0; k < HID + EMB; k++) acc += row[k] * w1[(size_t)k * HID + j];
        hid[j] = acc >= 0.f ? acc : 0.02f * acc;
    }
    __syncthreads();

    if (tid < OUTC) {
        float acc = b2[tid];
#pragma unroll 4
        for (int k = 0; k < HID; k++) acc += hid[k] * w2[(size_t)k * OUTC + tid];
        const int XT = BATCH * TSTEPS * 3;
        const int XR = BATCH * TSTEPS * 216;
        if (tid < 216)       out[XT + bt * 216 + tid] = acc;
        else if (tid == 216) out[XT + XR + bt] = acc;
        else                 out[XT + XR + BATCH * TSTEPS + bt] = acc;
    }
}

// ============================================================================
extern "C" void kernel_launch(void* const* d_in, const int* in_sizes, int n_in,
                              void* d_out, int out_size) {
    const float* pe     = (const float*)d_in[0];
    const float* coords = (const float*)d_in[1];
    const float* traj   = (const float*)d_in[2];
    const float* hw1    = (const float*)d_in[3];
    const float* hb1    = (const float*)d_in[4];
    const float* hw2    = (const float*)d_in[5];
    const float* hb2    = (const float*)d_in[6];
    const float* aw1    = (const float*)d_in[7];
    const float* ab1    = (const float*)d_in[8];
    const float* aw2    = (const float*)d_in[9];
    const float* ab2    = (const float*)d_in[10];
    const int*   np     = (const int*)d_in[11];
    float* out = (float*)d_out;

    static bool attr_set = false;
    if (!attr_set) {
        cudaFuncSetAttribute(kgemm, cudaFuncAttributeMaxDynamicSharedMemorySize, 98304);
        cudaFuncSetAttribute(k3b, cudaFuncAttributeMaxDynamicSharedMemorySize, K3_SMEM);
        attr_set = true;
    }

    k0a_conv<<<NPTS * 64 / 256, 256>>>(pe);                      // launch 1
    k0w_conv<<<dim3(16, 16), dim3(32, 8)>>>(hw1);                // launch 2
    kgemm<<<dim3(NPTS / 256, HID / 128), 256, 98304>>>();        // launch 3
    k3b<<<NPTS / 128, 256, K3_SMEM>>>(coords, traj, hw1, hb1,    // launch 4 (profiled)
                                      hw2, hb2);
    k4_soft<<<BATCH * TSTEPS, 256>>>(np, out);                   // launch 5
    k5a<<<dim3(BATCH, HID / 128, 8), 128>>>(pe, np);             // launch 6
    k6_act<<<BATCH * TSTEPS, 256>>>(traj, aw1, ab1, aw2, ab2, out); // launch 7
}

// round 7
// speedup vs baseline: 1.9350x; 1.3710x over previous
#include <cuda_runtime.h>
#include <cuda_bf16.h>
#include <cstdint>

#define NPTS    16384
#define BATCH   16
#define HID     512
#define EMB     64
#define TSTEPS  8
#define OUTC    218
#define NSTEP   48           // K = 1536 in 32-wide k-steps
#define NCHUNK5 16

// ---- scratch (static device allocations) ----
__device__ __align__(128) __nv_bfloat16 g_A2[NPTS * 1024];   // [ah | al] per row
__device__ __align__(128) __nv_bfloat16 g_Wc[HID * 1024];    // [wh | wl] per n-row, K contig
__device__ float g_vt[HID * TSTEPS];          // [j][t]
__device__ float g_logitsT[TSTEPS * NPTS];    // [t][p]
__device__ float g_newcT[TSTEPS * 3 * NPTS];  // [t*3+c][p]
__device__ float g_pp[BATCH * NCHUNK5 * HID];

// ============================ PTX helpers ====================================
__device__ __forceinline__ uint32_t smem_u32(const void* p) {
    uint32_t a;
    asm("{ .reg .u64 t; cvta.to.shared.u64 t, %1; cvt.u32.u64 %0, t; }" : "=r"(a) : "l"(p));
    return a;
}
#define CP_ASYNC16(dst, src) \
    asm volatile("cp.async.cg.shared.global [%0], [%1], 16;" :: "r"(dst), "l"(src) : "memory")
#define CP_COMMIT() asm volatile("cp.async.commit_group;" ::: "memory")
#define CP_WAIT(n)  asm volatile("cp.async.wait_group %0;" :: "n"(n) : "memory")

#define LDSM4(d, a) \
    asm volatile("ldmatrix.sync.aligned.m8n8.x4.shared.b16 {%0,%1,%2,%3}, [%4];" \
                 : "=r"((d)[0]), "=r"((d)[1]), "=r"((d)[2]), "=r"((d)[3]) : "r"(a))

#define MMA_BF16(c, a, b) \
    asm volatile( \
        "mma.sync.aligned.m16n8k16.row.col.f32.bf16.bf16.f32 " \
        "{%0,%1,%2,%3},{%4,%5,%6,%7},{%8,%9},{%0,%1,%2,%3};" \
        : "+f"((c)[0]), "+f"((c)[1]), "+f"((c)[2]), "+f"((c)[3]) \
        : "r"((a)[0]), "r"((a)[1]), "r"((a)[2]), "r"((a)[3]), "r"((b)[0]), "r"((b)[1]))

// ============================================================================
// K0a: split point_embeds fp32 -> bf16 hi/lo into g_A2 [16384][1024]
// ============================================================================
__global__ __launch_bounds__(256) void k0a_conv(const float* __restrict__ pe) {
    int idx = blockIdx.x * 256 + threadIdx.x;
    int row = idx >> 6, g = idx & 63;
    const float* src = pe + (size_t)row * HID + g * 8;
    float4 f0 = *(const float4*)src;
    float4 f1 = *(const float4*)(src + 4);
    float f[8] = {f0.x, f0.y, f0.z, f0.w, f1.x, f1.y, f1.z, f1.w};
    __align__(16) __nv_bfloat16 hi[8], lo[8];
#pragma unroll
    for (int i = 0; i < 8; i++) {
        hi[i] = __float2bfloat16(f[i]);
        lo[i] = __float2bfloat16(f[i] - __bfloat162float(hi[i]));
    }
    __nv_bfloat16* dst = g_A2 + (size_t)row * 1024 + g * 8;
    *(uint4*)dst = *(const uint4*)hi;
    *(uint4*)(dst + 512) = *(const uint4*)lo;
}

// ============================================================================
// K0w: (y<16) coalesced transpose+split of hm_w1[:512] -> g_Wc;
//      (y==16) vt[j][t] = hm_b1[j] + traj[t].hm_w1[512:][:,j]
// ============================================================================
__global__ void k0w_conv(const float* __restrict__ w1, const float* __restrict__ b1,
                         const float* __restrict__ traj) {
    __shared__ float s[32][33];
    const int tx = threadIdx.x, ty = threadIdx.y;
    if (blockIdx.y == 16) {
        const int j = blockIdx.x * 32 + tx;
        const int t = ty;
        float acc = b1[j];
#pragma unroll 8
        for (int e = 0; e < EMB; e++)
            acc += traj[t * EMB + e] * w1[(size_t)(HID + e) * HID + j];
        g_vt[j * TSTEPS + t] = acc;
        return;
    }
    const int kb = blockIdx.y * 32, nb = blockIdx.x * 32;
#pragma unroll
    for (int i = 0; i < 4; i++) {
        int k = ty + i * 8;
        s[k][tx] = w1[(size_t)(kb + k) * HID + nb + tx];
    }
    __syncthreads();
#pragma unroll
    for (int i = 0; i < 4; i++) {
        int nr = ty + i * 8;
        float f = s[tx][nr];
        __nv_bfloat16 hi = __float2bfloat16(f);
        __nv_bfloat16 lo = __float2bfloat16(f - __bfloat162float(hi));
        g_Wc[(size_t)(nb + nr) * 1024 + kb + tx] = hi;
        g_Wc[(size_t)(nb + nr) * 1024 + 512 + kb + tx] = lo;
    }
}

// ============================================================================
// K5a: segment max-pool phase 1 -> g_pp [b][chunk16][512]
// ============================================================================
__global__ __launch_bounds__(128) void k5a(const float* __restrict__ pe,
                                           const int* __restrict__ np) {
    const int b = blockIdx.x;
    const int col = blockIdx.y * 128 + threadIdx.x;
    const int chunk = blockIdx.z;
    int start = 0;
    for (int i = 0; i < b; i++) start += np[i];
    const int len = np[b];
    const int c0 = start + (chunk * len) / NCHUNK5;
    const int c1 = start + ((chunk + 1) * len) / NCHUNK5;

    float m0 = -1e30f, m1 = -1e30f, m2 = -1e30f, m3 = -1e30f;
    int p = c0;
    for (; p + 3 < c1; p += 4) {
        m0 = fmaxf(m0, pe[(size_t)p * HID + col]);
        m1 = fmaxf(m1, pe[(size_t)(p + 1) * HID + col]);
        m2 = fmaxf(m2, pe[(size_t)(p + 2) * HID + col]);
        m3 = fmaxf(m3, pe[(size_t)(p + 3) * HID + col]);
    }
    for (; p < c1; p++) m0 = fmaxf(m0, pe[(size_t)p * HID + col]);
    g_pp[(b * NCHUNK5 + chunk) * HID + col] = fmaxf(fmaxf(m0, m1), fmaxf(m2, m3));
}

// ============================================================================
// KGEMM v4 (+ fused heatmap head):
//   CTA 64m x 512n, 512 thr (16 warps 2m x 8n), warp tile 32x64.
//   2-stage cp.async K=32, 36864 B/stage -> 72KB, 2 CTAs/SM, grid 256.
//   Epilogue: u rows complete in-CTA -> lrelu(u+vt).w2 -> logitsT/newcT direct.
// ============================================================================
#define STAGE_BYTES 36864
#define SMEM_KG (2 * STAGE_BYTES)

__global__ __launch_bounds__(512) void kgemm(const float* __restrict__ coords,
                                             const float* __restrict__ w2,
                                             const float* __restrict__ b2) {
    extern __shared__ char smem[];
    const uint32_t sb = smem_u32(smem);
    const int tid = threadIdx.x;
    const int lane = tid & 31, w = tid >> 5;
    const int wm = w >> 3, wn = w & 7;          // 2(m) x 8(n)
    const int bm = blockIdx.x;
    const int ti = lane >> 3, r = lane & 7;

    float acc[2][8][4];
#pragma unroll
    for (int i = 0; i < 2; i++)
#pragma unroll
        for (int j = 0; j < 8; j++)
#pragma unroll
            for (int q = 0; q < 4; q++) acc[i][j][q] = 0.f;

    const char* Ab = (const char*)g_A2 + (size_t)bm * 64 * 2048;
    const char* Bb = (const char*)g_Wc;

    auto stage_load = [&](int s) {
        const int buf = s & 1;
        const int aof = (s < 16) ? s * 32 : (s < 32) ? 512 + (s - 16) * 32 : (s - 32) * 32;
        const int bof = (s < 32) ? (s & 15) * 32 : 512 + (s - 32) * 32;
        const uint32_t dA = sb + buf * STAGE_BYTES;
        const uint32_t dB = dA + 4096;
        if (tid < 256) {
            int m = tid >> 2, kg = tid & 3;
            uint32_t off = (uint32_t)((((m >> 3) * 4 + kg) * 8 + (m & 7)) * 16);
            CP_ASYNC16(dA + off, Ab + (size_t)m * 2048 + (size_t)(aof + kg * 8) * 2);
        }
#pragma unroll
        for (int h = 0; h < 4; h++) {
            int q = h * 512 + tid;
            int n = q >> 2, kg = q & 3;
            uint32_t off = (uint32_t)((((n >> 3) * 4 + kg) * 8 + (n & 7)) * 16);
            CP_ASYNC16(dB + off, Bb + (size_t)n * 2048 + (size_t)(bof + kg * 8) * 2);
        }
        CP_COMMIT();
    };

    stage_load(0);

    for (int s = 0; s < NSTEP; s++) {
        __syncthreads();    // everyone done reading buf (s+1)&1 from step s-1
        if (s + 1 < NSTEP) stage_load(s + 1); else CP_COMMIT();
        CP_WAIT(1);
        __syncthreads();
        const uint32_t sA = sb + (s & 1) * STAGE_BYTES;
        const uint32_t sB = sA + 4096;
#pragma unroll
        for (int kk = 0; kk < 2; kk++) {
            uint32_t af[2][4];
#pragma unroll
            for (int i = 0; i < 2; i++) {
                int m8 = wm * 4 + i * 2 + (ti & 1);
                int k8 = kk * 2 + (ti >> 1);
                LDSM4(af[i], sA + (uint32_t)(((m8 * 4 + k8) * 8 + r) * 16));
            }
            uint32_t bf[4][4];
#pragma unroll
            for (int pj = 0; pj < 4; pj++) {
                int n8 = wn * 8 + pj * 2 + (ti >> 1);
                int k8 = kk * 2 + (ti & 1);
                LDSM4(bf[pj], sB + (uint32_t)(((n8 * 4 + k8) * 8 + r) * 16));
            }
#pragma unroll
            for (int i = 0; i < 2; i++)
#pragma unroll
                for (int j = 0; j < 8; j++)
                    MMA_BF16(acc[i][j], af[i], &bf[j >> 1][(j & 1) * 2]);
        }
    }
    CP_WAIT(0);
    __syncthreads();

    // ---- fused heatmap head epilogue ----
    float* vts  = (float*)smem;            // [512][8]  16KB
    float* w2s  = (float*)(smem + 16384);  // [512][4]   8KB
    float* rbuf = (float*)(smem + 24576);  // [16 rows][8 wn][32] 16KB
    for (int idx = tid; idx < HID * TSTEPS; idx += 512) vts[idx] = g_vt[idx];
    for (int idx = tid; idx < HID * 4; idx += 512) w2s[idx] = w2[idx];
    __syncthreads();
    const float b2v[4] = {b2[0], b2[1], b2[2], b2[3]};

#pragma unroll
    for (int i = 0; i < 2; i++) {
#pragma unroll
        for (int qh = 0; qh < 2; qh++) {
            float part[32];
#pragma unroll
            for (int v = 0; v < 32; v++) part[v] = 0.f;
#pragma unroll
            for (int j = 0; j < 8; j++) {
#pragma unroll
                for (int col = 0; col < 2; col++) {
                    const float u = acc[i][j][qh * 2 + col];
                    const int jl = wn * 64 + j * 8 + (lane & 3) * 2 + col;
                    const float* vt8 = vts + jl * 8;
                    float4 wv = *(const float4*)(w2s + jl * 4);
#pragma unroll
                    for (int t = 0; t < 8; t++) {
                        float x = u + vt8[t];
                        float h = fmaxf(x, 0.02f * x);
                        part[t * 4 + 0] += h * wv.x;
                        part[t * 4 + 1] += h * wv.y;
                        part[t * 4 + 2] += h * wv.z;
                        part[t * 4 + 3] += h * wv.w;
                    }
                }
            }
            // reduce over the 4 lanes sharing this m-row (lane&3)
#pragma unroll
            for (int o = 1; o <= 2; o <<= 1)
#pragma unroll
                for (int v = 0; v < 32; v++)
                    part[v] += __shfl_xor_sync(0xffffffffu, part[v], o);
            if ((lane & 3) == 0) {
                int row = wm * 8 + (lane >> 2);
                float* d = rbuf + (row * 8 + wn) * 32;
#pragma unroll
                for (int v = 0; v < 32; v++) d[v] = part[v];
            }
            __syncthreads();
            {
                const int row = tid >> 5, v = tid & 31;
                const float* src = rbuf + row * 256 + v;
                float sum = 0.f;
#pragma unroll
                for (int k = 0; k < 8; k++) sum += src[k * 32];
                const int m_g = bm * 64 + (row >> 3) * 32 + i * 16 + qh * 8 + (row & 7);
                const int t = v >> 2, c = v & 3;
                if (c == 0)
                    g_logitsT[t * NPTS + m_g] = sum + b2v[0];
                else
                    g_newcT[(t * 3 + c - 1) * NPTS + m_g] =
                        coords[m_g * 3 + (c - 1)] + sum + b2v[c];
            }
            __syncthreads();
        }
    }
}

// ============================================================================
// K4: per (segment, t): stable softmax + weighted coord sum -> out[0:384]
//     coalesced reads from transposed logits/newc, 512 thr
// ============================================================================
__global__ __launch_bounds__(512) void k4_soft(const int* __restrict__ np,
                                               float* __restrict__ out) {
    const int b = blockIdx.x >> 3, t = blockIdx.x & 7;
    const int tid = threadIdx.x, lane = tid & 31, warp = tid >> 5;
    int start = 0;
    for (int i = 0; i < b; i++) start += np[i];
    const int end = start + np[b];
    const float* lg = g_logitsT + (size_t)t * NPTS;
    const float* nx = g_newcT + (size_t)(t * 3 + 0) * NPTS;
    const float* ny = g_newcT + (size_t)(t * 3 + 1) * NPTS;
    const float* nz = g_newcT + (size_t)(t * 3 + 2) * NPTS;

    __shared__ float sred[16][4];
    __shared__ float mshared;

    float m = -1e30f;
    for (int p = start + tid; p < end; p += 512) m = fmaxf(m, lg[p]);
#pragma unroll
    for (int o = 16; o > 0; o >>= 1) m = fmaxf(m, __shfl_down_sync(0xffffffffu, m, o));
    if (lane == 0) sred[warp][0] = m;
    __syncthreads();
    if (tid == 0) {
        float v = sred[0][0];
        for (int i = 1; i < 16; i++) v = fmaxf(v, sred[i][0]);
        mshared = v;
    }
    __syncthreads();
    const float mx = mshared;

    float s = 0.f, sx = 0.f, sy = 0.f, sz = 0.f;
    for (int p = start + tid; p < end; p += 512) {
        float e = expf(lg[p] - mx);
        s += e; sx += e * nx[p]; sy += e * ny[p]; sz += e * nz[p];
    }
#pragma unroll
    for (int o = 16; o > 0; o >>= 1) {
        s  += __shfl_down_sync(0xffffffffu, s,  o);
        sx += __shfl_down_sync(0xffffffffu, sx, o);
        sy += __shfl_down_sync(0xffffffffu, sy, o);
        sz += __shfl_down_sync(0xffffffffu, sz, o);
    }
    if (lane == 0) { sred[warp][0] = s; sred[warp][1] = sx; sred[warp][2] = sy; sred[warp][3] = sz; }
    __syncthreads();
    if (tid == 0) {
        float ts = 0, tx = 0, ty = 0, tz = 0;
        for (int i = 0; i < 16; i++) { ts += sred[i][0]; tx += sred[i][1]; ty += sred[i][2]; tz += sred[i][3]; }
        float inv = 1.f / ts;
        out[(b * 8 + t) * 3 + 0] = tx * inv;
        out[(b * 8 + t) * 3 + 1] = ty * inv;
        out[(b * 8 + t) * 3 + 2] = tz * inv;
    }
}

// ============================================================================
// K6: act MLP per (b,t), 512 thr, k-split layer1, UNIFORM barriers only
// ============================================================================
__global__ __launch_bounds__(512) void k6_act(const float* __restrict__ traj,
                                              const float* __restrict__ w1,
                                              const float* __restrict__ b1,
                                              const float* __restrict__ w2,
                                              const float* __restrict__ b2,
                                              float* __restrict__ out) {
    __shared__ float row[HID + EMB];
    __shared__ float hid[HID];
    __shared__ float sbuf[4][128][4];
    __shared__ float sred2[OUTC];
    const int bt = blockIdx.x;
    const int b = bt >> 3, t = bt & 7;
    const int tid = threadIdx.x;

    if (tid < HID) {
        float m = -1e30f;
#pragma unroll
        for (int c = 0; c < NCHUNK5; c++) m = fmaxf(m, g_pp[(b * NCHUNK5 + c) * HID + tid]);
        row[tid] = m;
    }
    if (tid < EMB) row[HID + tid] = traj[t * EMB + tid];
    __syncthreads();

    // layer 1: 4-way k split, float4 over j
    {
        const int jq = tid & 127, kh = tid >> 7;
        const int k0 = kh * 144, k1 = k0 + 144;
        float4 a = {0.f, 0.f, 0.f, 0.f};
#pragma unroll 4
        for (int k = k0; k < k1; k++) {
            float f = row[k];
            float4 wv = *(const float4*)(w1 + (size_t)k * HID + jq * 4);
            a.x += f * wv.x; a.y += f * wv.y; a.z += f * wv.z; a.w += f * wv.w;
        }
        sbuf[kh][jq][0] = a.x; sbuf[kh][jq][1] = a.y;
        sbuf[kh][jq][2] = a.z; sbuf[kh][jq][3] = a.w;
    }
    __syncthreads();
    if (tid < 128) {
#pragma unroll
        for (int c = 0; c < 4; c++) {
            int j = tid * 4 + c;
            float v = sbuf[0][tid][c] + sbuf[1][tid][c] + sbuf[2][tid][c] + sbuf[3][tid][c] + b1[j];
            hid[j] = v >= 0.f ? v : 0.02f * v;
        }
    }
    __syncthreads();

    // layer 2: 2-way k split over 218 outputs; single uniform barrier
    const bool active = (tid < 2 * OUTC);
    const int h = active ? (tid >= OUTC ? 1 : 0) : 0;
    const int o = active ? (tid - h * OUTC) : 0;
    float a = 0.f;
    if (active) {
        const int k0 = h * 256, k1 = k0 + 256;
#pragma unroll 4
        for (int k = k0; k < k1; k++) a += hid[k] * w2[(size_t)k * OUTC + o];
        if (h) sred2[o] = a;
    }
    __syncthreads();
    if (active && !h) {
        float tot = a + sred2[o] + b2[o];
        const int XT = BATCH * TSTEPS * 3;
        const int XR = BATCH * TSTEPS * 216;
        if (o < 216)       out[XT + bt * 216 + o] = tot;
        else if (o == 216) out[XT + XR + bt] = tot;
        else               out[XT + XR + BATCH * TSTEPS + bt] = tot;
    }
}

// ============================================================================
extern "C" void kernel_launch(void* const* d_in, const int* in_sizes, int n_in,
                              void* d_out, int out_size) {
    const float* pe     = (const float*)d_in[0];
    const float* coords = (const float*)d_in[1];
    const float* traj   = (const float*)d_in[2];
    const float* hw1    = (const float*)d_in[3];
    const float* hb1    = (const float*)d_in[4];
    const float* hw2    = (const float*)d_in[5];
    const float* hb2    = (const float*)d_in[6];
    const float* aw1    = (const float*)d_in[7];
    const float* ab1    = (const float*)d_in[8];
    const float* aw2    = (const float*)d_in[9];
    const float* ab2    = (const float*)d_in[10];
    const int*   np     = (const int*)d_in[11];
    float* out = (float*)d_out;

    static bool attr_set = false;
    if (!attr_set) {
        cudaFuncSetAttribute(kgemm, cudaFuncAttributeMaxDynamicSharedMemorySize, SMEM_KG);
        attr_set = true;
    }

    k0a_conv<<<NPTS * 64 / 256, 256>>>(pe);                          // 1
    k0w_conv<<<dim3(16, 17), dim3(32, 8)>>>(hw1, hb1, traj);         // 2
    k5a<<<dim3(BATCH, HID / 128, NCHUNK5), 128>>>(pe, np);           // 3
    kgemm<<<NPTS / 64, 512, SMEM_KG>>>(coords, hw2, hb2);            // 4 (profiled)
    k4_soft<<<BATCH * TSTEPS, 512>>>(np, out);                       // 5
    k6_act<<<BATCH * TSTEPS, 512>>>(traj, aw1, ab1, aw2, ab2, out);  // 6
}

// round 8
// speedup vs baseline: 2.2701x; 1.1732x over previous
#include <cuda_runtime.h>
#include <cuda_bf16.h>
#include <cstdint>

#define NPTS    16384
#define BATCH   16
#define HID     512
#define EMB     64
#define TSTEPS  8
#define OUTC    218
#define NSTEP   48           // K = 1536 in 32-wide k-steps
#define NCHUNK5 16

// ---- scratch (static device allocations) ----
__device__ __align__(128) __nv_bfloat16 g_A2[NPTS * 1024];   // [ah | al] per row
__device__ __align__(128) __nv_bfloat16 g_Wc[HID * 1024];    // [wh | wl] per n-row, K contig
__device__ float g_vt[HID * TSTEPS];          // [j][t]
__device__ float g_part[4 * NPTS * 32];       // [bn][p][t*4+c] head partials (8 MB)
__device__ float g_logitsT[TSTEPS * NPTS];    // [t][p]
__device__ float g_newcT[TSTEPS * 3 * NPTS];  // [t*3+c][p]
__device__ float g_pp[BATCH * NCHUNK5 * HID];

// ============================ PTX helpers ====================================
__device__ __forceinline__ uint32_t smem_u32(const void* p) {
    uint32_t a;
    asm("{ .reg .u64 t; cvta.to.shared.u64 t, %1; cvt.u32.u64 %0, t; }" : "=r"(a) : "l"(p));
    return a;
}
#define CP_ASYNC16(dst, src) \
    asm volatile("cp.async.cg.shared.global [%0], [%1], 16;" :: "r"(dst), "l"(src) : "memory")
#define CP_COMMIT() asm volatile("cp.async.commit_group;" ::: "memory")
#define CP_WAIT(n)  asm volatile("cp.async.wait_group %0;" :: "n"(n) : "memory")

#define LDSM4(d, a) \
    asm volatile("ldmatrix.sync.aligned.m8n8.x4.shared.b16 {%0,%1,%2,%3}, [%4];" \
                 : "=r"((d)[0]), "=r"((d)[1]), "=r"((d)[2]), "=r"((d)[3]) : "r"(a))

#define MMA_BF16(c, a, b) \
    asm volatile( \
        "mma.sync.aligned.m16n8k16.row.col.f32.bf16.bf16.f32 " \
        "{%0,%1,%2,%3},{%4,%5,%6,%7},{%8,%9},{%0,%1,%2,%3};" \
        : "+f"((c)[0]), "+f"((c)[1]), "+f"((c)[2]), "+f"((c)[3]) \
        : "r"((a)[0]), "r"((a)[1]), "r"((a)[2]), "r"((a)[3]), "r"((b)[0]), "r"((b)[1]))

// ============================================================================
// K0a: split point_embeds fp32 -> bf16 hi/lo into g_A2 [16384][1024]
// ============================================================================
__global__ __launch_bounds__(256) void k0a_conv(const float* __restrict__ pe) {
    int idx = blockIdx.x * 256 + threadIdx.x;
    int row = idx >> 6, g = idx & 63;
    const float* src = pe + (size_t)row * HID + g * 8;
    float4 f0 = *(const float4*)src;
    float4 f1 = *(const float4*)(src + 4);
    float f[8] = {f0.x, f0.y, f0.z, f0.w, f1.x, f1.y, f1.z, f1.w};
    __align__(16) __nv_bfloat16 hi[8], lo[8];
#pragma unroll
    for (int i = 0; i < 8; i++) {
        hi[i] = __float2bfloat16(f[i]);
        lo[i] = __float2bfloat16(f[i] - __bfloat162float(hi[i]));
    }
    __nv_bfloat16* dst = g_A2 + (size_t)row * 1024 + g * 8;
    *(uint4*)dst = *(const uint4*)hi;
    *(uint4*)(dst + 512) = *(const uint4*)lo;
}

// ============================================================================
// K0w: (y<16) coalesced transpose+split of hm_w1[:512] -> g_Wc;
//      (y==16) vt[j][t] = hm_b1[j] + traj[t].hm_w1[512:][:,j]
// ============================================================================
__global__ void k0w_conv(const float* __restrict__ w1, const float* __restrict__ b1,
                         const float* __restrict__ traj) {
    __shared__ float s[32][33];
    const int tx = threadIdx.x, ty = threadIdx.y;
    if (blockIdx.y == 16) {
        const int j = blockIdx.x * 32 + tx;
        const int t = ty;
        float acc = b1[j];
#pragma unroll 8
        for (int e = 0; e < EMB; e++)
            acc += traj[t * EMB + e] * w1[(size_t)(HID + e) * HID + j];
        g_vt[j * TSTEPS + t] = acc;
        return;
    }
    const int kb = blockIdx.y * 32, nb = blockIdx.x * 32;
#pragma unroll
    for (int i = 0; i < 4; i++) {
        int k = ty + i * 8;
        s[k][tx] = w1[(size_t)(kb + k) * HID + nb + tx];
    }
    __syncthreads();
#pragma unroll
    for (int i = 0; i < 4; i++) {
        int nr = ty + i * 8;
        float f = s[tx][nr];
        __nv_bfloat16 hi = __float2bfloat16(f);
        __nv_bfloat16 lo = __float2bfloat16(f - __bfloat162float(hi));
        g_Wc[(size_t)(nb + nr) * 1024 + kb + tx] = hi;
        g_Wc[(size_t)(nb + nr) * 1024 + 512 + kb + tx] = lo;
    }
}

// ============================================================================
// K5a: segment max-pool phase 1 -> g_pp [b][chunk16][512]
// ============================================================================
__global__ __launch_bounds__(128) void k5a(const float* __restrict__ pe,
                                           const int* __restrict__ np) {
    const int b = blockIdx.x;
    const int col = blockIdx.y * 128 + threadIdx.x;
    const int chunk = blockIdx.z;
    int start = 0;
    for (int i = 0; i < b; i++) start += np[i];
    const int len = np[b];
    const int c0 = start + (chunk * len) / NCHUNK5;
    const int c1 = start + ((chunk + 1) * len) / NCHUNK5;

    float m0 = -1e30f, m1 = -1e30f, m2 = -1e30f, m3 = -1e30f;
    int p = c0;
    for (; p + 3 < c1; p += 4) {
        m0 = fmaxf(m0, pe[(size_t)p * HID + col]);
        m1 = fmaxf(m1, pe[(size_t)(p + 1) * HID + col]);
        m2 = fmaxf(m2, pe[(size_t)(p + 2) * HID + col]);
        m3 = fmaxf(m3, pe[(size_t)(p + 3) * HID + col]);
    }
    for (; p < c1; p++) m0 = fmaxf(m0, pe[(size_t)p * HID + col]);
    g_pp[(b * NCHUNK5 + chunk) * HID + col] = fmaxf(fmaxf(m0, m1), fmaxf(m2, m3));
}

// ============================================================================
// KGEMM v5: CTA 128m x 128n, 256 thr (8 warps 2m x 4n), warp 64x32,
//   4-stage cp.async K=32 (16KB/stage -> 64KB, 2 CTAs/SM).
//   Epilogue: head partials over this CTA's 128 cols -> g_part[bn][p][32].
// ============================================================================
#define STG_B   16384
#define SMEM_KG (4 * STG_B)

__global__ __launch_bounds__(256, 2) void kgemm(const float* __restrict__ w2) {
    extern __shared__ char smem[];
    const uint32_t sb = smem_u32(smem);
    const int tid = threadIdx.x;
    const int lane = tid & 31, w = tid >> 5;
    const int wm = w >> 2, wn = w & 3;          // 2(m) x 4(n)
    const int bm = blockIdx.x, bn = blockIdx.y;
    const int ti = lane >> 3, r = lane & 7;

    float acc[4][4][4];
#pragma unroll
    for (int i = 0; i < 4; i++)
#pragma unroll
        for (int j = 0; j < 4; j++)
#pragma unroll
            for (int q = 0; q < 4; q++) acc[i][j][q] = 0.f;

    const char* Ab = (const char*)g_A2 + (size_t)bm * 128 * 2048;
    const char* Bb = (const char*)g_Wc + (size_t)bn * 128 * 2048;

    auto stage_load = [&](int s) {
        const int buf = s & 3;
        const int aof = (s < 16) ? s * 32 : (s < 32) ? 512 + (s - 16) * 32 : (s - 32) * 32;
        const int bof = (s < 32) ? (s & 15) * 32 : 512 + (s - 32) * 32;
        const uint32_t dA = sb + buf * STG_B;
        const uint32_t dB = dA + 8192;
#pragma unroll
        for (int h = 0; h < 2; h++) {
            int q = h * 256 + tid;
            int m = q >> 2, kg = q & 3;
            uint32_t off = (uint32_t)((((m >> 3) * 4 + kg) * 8 + (m & 7)) * 16);
            CP_ASYNC16(dA + off, Ab + (size_t)m * 2048 + (size_t)(aof + kg * 8) * 2);
            CP_ASYNC16(dB + off, Bb + (size_t)m * 2048 + (size_t)(bof + kg * 8) * 2);
        }
        CP_COMMIT();
    };

    stage_load(0); stage_load(1); stage_load(2);

    for (int s = 0; s < NSTEP; s++) {
        CP_WAIT(2);
        __syncthreads();
        const uint32_t sA = sb + (s & 3) * STG_B;
        const uint32_t sB = sA + 8192;
#pragma unroll
        for (int kk = 0; kk < 2; kk++) {
            uint32_t af[4][4];
#pragma unroll
            for (int i = 0; i < 4; i++) {
                int m8 = (wm * 4 + i) * 2 + (ti & 1);
                int k8 = kk * 2 + (ti >> 1);
                LDSM4(af[i], sA + (uint32_t)(((m8 * 4 + k8) * 8 + r) * 16));
            }
            uint32_t bf[2][4];
#pragma unroll
            for (int pj = 0; pj < 2; pj++) {
                int n8 = wn * 4 + pj * 2 + (ti >> 1);
                int k8 = kk * 2 + (ti & 1);
                LDSM4(bf[pj], sB + (uint32_t)(((n8 * 4 + k8) * 8 + r) * 16));
            }
#pragma unroll
            for (int i = 0; i < 4; i++)
#pragma unroll
                for (int j = 0; j < 4; j++)
                    MMA_BF16(acc[i][j], af[i], &bf[j >> 1][(j & 1) * 2]);
        }
        if (s + 3 < NSTEP) stage_load(s + 3); else CP_COMMIT();
    }
    CP_WAIT(0);
    __syncthreads();

    // ---- fused head partial epilogue (this CTA's 128 cols) ----
    float* vts  = (float*)smem;            // [128][8]  4KB
    float* w2s  = (float*)(smem + 4096);   // [128][4]  2KB
    float* rbuf = (float*)(smem + 8192);   // [16 rows][4 wn][32] 8KB
    for (int idx = tid; idx < 128 * TSTEPS; idx += 256) vts[idx] = g_vt[bn * 1024 + idx];
    if (tid < 128 * 4 / 2) {               // 512 floats via 256 thr x 2
        w2s[tid] = w2[bn * 512 + tid];
        w2s[tid + 256] = w2[bn * 512 + tid + 256];
    }
    __syncthreads();

#pragma unroll
    for (int i = 0; i < 4; i++) {
#pragma unroll
        for (int half = 0; half < 2; half++) {
            float part[32];
#pragma unroll
            for (int v = 0; v < 32; v++) part[v] = 0.f;
#pragma unroll
            for (int j = 0; j < 4; j++) {
#pragma unroll
                for (int col = 0; col < 2; col++) {
                    const float u = acc[i][j][half * 2 + col];
                    const int nl = wn * 32 + j * 8 + (lane & 3) * 2 + col;
                    const float* vt8 = vts + nl * 8;
                    float4 wv = *(const float4*)(w2s + nl * 4);
#pragma unroll
                    for (int t = 0; t < 8; t++) {
                        float x = u + vt8[t];
                        float h = fmaxf(x, 0.02f * x);
                        part[t * 4 + 0] += h * wv.x;
                        part[t * 4 + 1] += h * wv.y;
                        part[t * 4 + 2] += h * wv.z;
                        part[t * 4 + 3] += h * wv.w;
                    }
                }
            }
#pragma unroll
            for (int o = 1; o <= 2; o <<= 1)
#pragma unroll
                for (int v = 0; v < 32; v++)
                    part[v] += __shfl_xor_sync(0xffffffffu, part[v], o);
            if ((lane & 3) == 0) {
                int row = wm * 8 + (lane >> 2);
                float* d = rbuf + (row * 4 + wn) * 32;
#pragma unroll
                for (int v = 0; v < 32; v++) d[v] = part[v];
            }
            __syncthreads();
#pragma unroll
            for (int sl = 0; sl < 2; sl++) {
                const int slot = sl * 256 + tid;
                const int row = slot >> 5, v = slot & 31;
                const float* src = rbuf + row * 128 + v;
                float sum = src[0] + src[32] + src[64] + src[96];
                const int m_g = bm * 128 + (row >> 3) * 64 + i * 16 + half * 8 + (row & 7);
                g_part[((size_t)bn * NPTS + m_g) * 32 + v] = sum;
            }
            __syncthreads();
        }
    }
}

// ============================================================================
// K3c: reduce 4 bn partials + bias + coords -> logitsT / newcT (transposed)
// ============================================================================
__global__ __launch_bounds__(256) void k3c(const float* __restrict__ coords,
                                           const float* __restrict__ b2) {
    __shared__ float su[64 * 33];
    const int tid = threadIdx.x;
    const int p0 = blockIdx.x * 64;

    float4 a[2] = {{0, 0, 0, 0}, {0, 0, 0, 0}};
#pragma unroll
    for (int bn = 0; bn < 4; bn++) {
#pragma unroll
        for (int it = 0; it < 2; it++) {
            int f = it * 256 + tid;                 // 512 float4 per block
            const float4 v = *(const float4*)(g_part +
                (((size_t)bn * NPTS + p0 + (f >> 3)) * 32 + (f & 7) * 4));
            a[it].x += v.x; a[it].y += v.y; a[it].z += v.z; a[it].w += v.w;
        }
    }
#pragma unroll
    for (int it = 0; it < 2; it++) {
        int f = it * 256 + tid;
        int p = f >> 3, v4 = f & 7;
        float* d = su + p * 33 + v4 * 4;
        d[0] = a[it].x; d[1] = a[it].y; d[2] = a[it].z; d[3] = a[it].w;
    }
    __syncthreads();
    const float b2v[4] = {b2[0], b2[1], b2[2], b2[3]};
#pragma unroll
    for (int it = 0; it < 8; it++) {
        int s = it * 256 + tid;                     // 2048 slots
        int v = s >> 6, pl = s & 63;
        int t = v >> 2, c = v & 3;
        int p = p0 + pl;
        float val = su[pl * 33 + v];
        if (c == 0)
            g_logitsT[t * NPTS + p] = val + b2v[0];
        else
            g_newcT[(t * 3 + c - 1) * NPTS + p] = val + b2v[c] + coords[p * 3 + c - 1];
    }
}

// ============================================================================
// K4: per (segment, t): stable softmax + weighted coord sum -> out[0:384]
// ============================================================================
__global__ __launch_bounds__(512) void k4_soft(const int* __restrict__ np,
                                               float* __restrict__ out) {
    const int b = blockIdx.x >> 3, t = blockIdx.x & 7;
    const int tid = threadIdx.x, lane = tid & 31, warp = tid >> 5;
    int start = 0;
    for (int i = 0; i < b; i++) start += np[i];
    const int end = start + np[b];
    const float* lg = g_logitsT + (size_t)t * NPTS;
    const float* nx = g_newcT + (size_t)(t * 3 + 0) * NPTS;
    const float* ny = g_newcT + (size_t)(t * 3 + 1) * NPTS;
    const float* nz = g_newcT + (size_t)(t * 3 + 2) * NPTS;

    __shared__ float sred[16][4];
    __shared__ float mshared;

    float m = -1e30f;
    for (int p = start + tid; p < end; p += 512) m = fmaxf(m, lg[p]);
#pragma unroll
    for (int o = 16; o > 0; o >>= 1) m = fmaxf(m, __shfl_down_sync(0xffffffffu, m, o));
    if (lane == 0) sred[warp][0] = m;
    __syncthreads();
    if (tid == 0) {
        float v = sred[0][0];
        for (int i = 1; i < 16; i++) v = fmaxf(v, sred[i][0]);
        mshared = v;
    }
    __syncthreads();
    const float mx = mshared;

    float s = 0.f, sx = 0.f, sy = 0.f, sz = 0.f;
    for (int p = start + tid; p < end; p += 512) {
        float e = expf(lg[p] - mx);
        s += e; sx += e * nx[p]; sy += e * ny[p]; sz += e * nz[p];
    }
#pragma unroll
    for (int o = 16; o > 0; o >>= 1) {
        s  += __shfl_down_sync(0xffffffffu, s,  o);
        sx += __shfl_down_sync(0xffffffffu, sx, o);
        sy += __shfl_down_sync(0xffffffffu, sy, o);
        sz += __shfl_down_sync(0xffffffffu, sz, o);
    }
    if (lane == 0) { sred[warp][0] = s; sred[warp][1] = sx; sred[warp][2] = sy; sred[warp][3] = sz; }
    __syncthreads();
    if (tid == 0) {
        float ts = 0, tx = 0, ty = 0, tz = 0;
        for (int i = 0; i < 16; i++) { ts += sred[i][0]; tx += sred[i][1]; ty += sred[i][2]; tz += sred[i][3]; }
        float inv = 1.f / ts;
        out[(b * 8 + t) * 3 + 0] = tx * inv;
        out[(b * 8 + t) * 3 + 1] = ty * inv;
        out[(b * 8 + t) * 3 + 2] = tz * inv;
    }
}

// ============================================================================
// K6: act MLP per (b,t), 512 thr, k-split layer1, uniform barriers
// ============================================================================
__global__ __launch_bounds__(512) void k6_act(const float* __restrict__ traj,
                                              const float* __restrict__ w1,
                                              const float* __restrict__ b1,
                                              const float* __restrict__ w2,
                                              const float* __restrict__ b2,
                                              float* __restrict__ out) {
    __shared__ float row[HID + EMB];
    __shared__ float hid[HID];
    __shared__ float sbuf[4][128][4];
    __shared__ float sred2[OUTC];
    const int bt = blockIdx.x;
    const int b = bt >> 3, t = bt & 7;
    const int tid = threadIdx.x;

    if (tid < HID) {
        float m = -1e30f;
#pragma unroll
        for (int c = 0; c < NCHUNK5; c++) m = fmaxf(m, g_pp[(b * NCHUNK5 + c) * HID + tid]);
        row[tid] = m;
    }
    if (tid < EMB) row[HID + tid] = traj[t * EMB + tid];
    __syncthreads();

    {
        const int jq = tid & 127, kh = tid >> 7;
        const int k0 = kh * 144, k1 = k0 + 144;
        float4 a = {0.f, 0.f, 0.f, 0.f};
#pragma unroll 4
        for (int k = k0; k < k1; k++) {
            float f = row[k];
            float4 wv = *(const float4*)(w1 + (size_t)k * HID + jq * 4);
            a.x += f * wv.x; a.y += f * wv.y; a.z += f * wv.z; a.w += f * wv.w;
        }
        sbuf[kh][jq][0] = a.x; sbuf[kh][jq][1] = a.y;
        sbuf[kh][jq][2] = a.z; sbuf[kh][jq][3] = a.w;
    }
    __syncthreads();
    if (tid < 128) {
#pragma unroll
        for (int c = 0; c < 4; c++) {
            int j = tid * 4 + c;
            float v = sbuf[0][tid][c] + sbuf[1][tid][c] + sbuf[2][tid][c] + sbuf[3][tid][c] + b1[j];
            hid[j] = v >= 0.f ? v : 0.02f * v;
        }
    }
    __syncthreads();

    const bool active = (tid < 2 * OUTC);
    const int h = active ? (tid >= OUTC ? 1 : 0) : 0;
    const int o = active ? (tid - h * OUTC) : 0;
    float a = 0.f;
    if (active) {
        const int k0 = h * 256, k1 = k0 + 256;
#pragma unroll 4
        for (int k = k0; k < k1; k++) a += hid[k] * w2[(size_t)k * OUTC + o];
        if (h) sred2[o] = a;
    }
    __syncthreads();
    if (active && !h) {
        float tot = a + sred2[o] + b2[o];
        const int XT = BATCH * TSTEPS * 3;
        const int XR = BATCH * TSTEPS * 216;
        if (o < 216)       out[XT + bt * 216 + o] = tot;
        else if (o == 216) out[XT + XR + bt] = tot;
        else               out[XT + XR + BATCH * TSTEPS + bt] = tot;
    }
}

// ============================================================================
extern "C" void kernel_launch(void* const* d_in, const int* in_sizes, int n_in,
                              void* d_out, int out_size) {
    const float* pe     = (const float*)d_in[0];
    const float* coords = (const float*)d_in[1];
    const float* traj   = (const float*)d_in[2];
    const float* hw1    = (const float*)d_in[3];
    const float* hb1    = (const float*)d_in[4];
    const float* hw2    = (const float*)d_in[5];
    const float* hb2    = (const float*)d_in[6];
    const float* aw1    = (const float*)d_in[7];
    const float* ab1    = (const float*)d_in[8];
    const float* aw2    = (const float*)d_in[9];
    const float* ab2    = (const float*)d_in[10];
    const int*   np     = (const int*)d_in[11];
    float* out = (float*)d_out;

    static bool attr_set = false;
    if (!attr_set) {
        cudaFuncSetAttribute(kgemm, cudaFuncAttributeMaxDynamicSharedMemorySize, SMEM_KG);
        attr_set = true;
    }

    k0a_conv<<<NPTS * 64 / 256, 256>>>(pe);                          // 1
    k0w_conv<<<dim3(16, 17), dim3(32, 8)>>>(hw1, hb1, traj);         // 2
    k5a<<<dim3(BATCH, HID / 128, NCHUNK5), 128>>>(pe, np);           // 3
    kgemm<<<dim3(NPTS / 128, 4), 256, SMEM_KG>>>(hw2);               // 4 (profiled)
    k3c<<<NPTS / 64, 256>>>(coords, hb2);                            // 5
    k4_soft<<<BATCH * TSTEPS, 512>>>(np, out);                       // 6
    k6_act<<<BATCH * TSTEPS, 512>>>(traj, aw1, ab1, aw2, ab2, out);  // 7
}

// round 9
// speedup vs baseline: 2.7102x; 1.1938x over previous
#include <cuda_runtime.h>
#include <cuda_fp16.h>
#include <cstdint>

#define NPTS    16384
#define BATCH   16
#define HID     512
#define EMB     64
#define TSTEPS  8
#define OUTC    218
#define NSTEP   32           // K = 1024 (fp16 2-term) in 32-wide k-steps
#define NCHUNK5 16

// ---- scratch (static device allocations) ----
__device__ __align__(128) __half g_A2[NPTS * 1024];   // [ah | al] per row
__device__ __align__(128) __half g_Wc[HID * 512];     // wh, [n][k] K contig
__device__ float g_vt[HID * TSTEPS];          // [j][t]
__device__ float g_part[4 * NPTS * 32];       // [bn][p][t*4+c] head partials (8 MB)
__device__ float g_logitsT[TSTEPS * NPTS];    // [t][p]
__device__ float g_newcT[TSTEPS * 3 * NPTS];  // [t*3+c][p]
__device__ float g_pp[BATCH * NCHUNK5 * HID];

// ============================ PTX helpers ====================================
__device__ __forceinline__ uint32_t smem_u32(const void* p) {
    uint32_t a;
    asm("{ .reg .u64 t; cvta.to.shared.u64 t, %1; cvt.u32.u64 %0, t; }" : "=r"(a) : "l"(p));
    return a;
}
#define CP_ASYNC16(dst, src) \
    asm volatile("cp.async.cg.shared.global [%0], [%1], 16;" :: "r"(dst), "l"(src) : "memory")
#define CP_COMMIT() asm volatile("cp.async.commit_group;" ::: "memory")
#define CP_WAIT(n)  asm volatile("cp.async.wait_group %0;" :: "n"(n) : "memory")

#define LDSM4(d, a) \
    asm volatile("ldmatrix.sync.aligned.m8n8.x4.shared.b16 {%0,%1,%2,%3}, [%4];" \
                 : "=r"((d)[0]), "=r"((d)[1]), "=r"((d)[2]), "=r"((d)[3]) : "r"(a))

#define MMA_F16(c, a, b) \
    asm volatile( \
        "mma.sync.aligned.m16n8k16.row.col.f32.f16.f16.f32 " \
        "{%0,%1,%2,%3},{%4,%5,%6,%7},{%8,%9},{%0,%1,%2,%3};" \
        : "+f"((c)[0]), "+f"((c)[1]), "+f"((c)[2]), "+f"((c)[3]) \
        : "r"((a)[0]), "r"((a)[1]), "r"((a)[2]), "r"((a)[3]), "r"((b)[0]), "r"((b)[1]))

// ============================================================================
// K0a: split point_embeds fp32 -> fp16 hi/lo into g_A2 [16384][1024]
// ============================================================================
__global__ __launch_bounds__(256) void k0a_conv(const float* __restrict__ pe) {
    int idx = blockIdx.x * 256 + threadIdx.x;
    int row = idx >> 6, g = idx & 63;
    const float* src = pe + (size_t)row * HID + g * 8;
    float4 f0 = *(const float4*)src;
    float4 f1 = *(const float4*)(src + 4);
    float f[8] = {f0.x, f0.y, f0.z, f0.w, f1.x, f1.y, f1.z, f1.w};
    __align__(16) __half hi[8], lo[8];
#pragma unroll
    for (int i = 0; i < 8; i++) {
        hi[i] = __float2half_rn(f[i]);
        lo[i] = __float2half_rn(f[i] - __half2float(hi[i]));
    }
    __half* dst = g_A2 + (size_t)row * 1024 + g * 8;
    *(uint4*)dst = *(const uint4*)hi;
    *(uint4*)(dst + 512) = *(const uint4*)lo;
}

// ============================================================================
// K0w: (y<16) coalesced transpose of hm_w1[:512] -> g_Wc (fp16);
//      (y==16) vt[j][t] = hm_b1[j] + traj[t].hm_w1[512:][:,j]
// ============================================================================
__global__ void k0w_conv(const float* __restrict__ w1, const float* __restrict__ b1,
                         const float* __restrict__ traj) {
    __shared__ float s[32][33];
    const int tx = threadIdx.x, ty = threadIdx.y;
    if (blockIdx.y == 16) {
        const int j = blockIdx.x * 32 + tx;
        const int t = ty;
        float acc = b1[j];
#pragma unroll 8
        for (int e = 0; e < EMB; e++)
            acc += traj[t * EMB + e] * w1[(size_t)(HID + e) * HID + j];
        g_vt[j * TSTEPS + t] = acc;
        return;
    }
    const int kb = blockIdx.y * 32, nb = blockIdx.x * 32;
#pragma unroll
    for (int i = 0; i < 4; i++) {
        int k = ty + i * 8;
        s[k][tx] = w1[(size_t)(kb + k) * HID + nb + tx];
    }
    __syncthreads();
#pragma unroll
    for (int i = 0; i < 4; i++) {
        int nr = ty + i * 8;
        g_Wc[(size_t)(nb + nr) * 512 + kb + tx] = __float2half_rn(s[tx][nr]);
    }
}

// ============================================================================
// K5a: segment max-pool phase 1 -> g_pp [b][chunk16][512]
// ============================================================================
__global__ __launch_bounds__(128) void k5a(const float* __restrict__ pe,
                                           const int* __restrict__ np) {
    const int b = blockIdx.x;
    const int col = blockIdx.y * 128 + threadIdx.x;
    const int chunk = blockIdx.z;
    int start = 0;
    for (int i = 0; i < b; i++) start += np[i];
    const int len = np[b];
    const int c0 = start + (chunk * len) / NCHUNK5;
    const int c1 = start + ((chunk + 1) * len) / NCHUNK5;

    float m0 = -1e30f, m1 = -1e30f, m2 = -1e30f, m3 = -1e30f;
    int p = c0;
    for (; p + 3 < c1; p += 4) {
        m0 = fmaxf(m0, pe[(size_t)p * HID + col]);
        m1 = fmaxf(m1, pe[(size_t)(p + 1) * HID + col]);
        m2 = fmaxf(m2, pe[(size_t)(p + 2) * HID + col]);
        m3 = fmaxf(m3, pe[(size_t)(p + 3) * HID + col]);
    }
    for (; p < c1; p++) m0 = fmaxf(m0, pe[(size_t)p * HID + col]);
    g_pp[(b * NCHUNK5 + chunk) * HID + col] = fmaxf(fmaxf(m0, m1), fmaxf(m2, m3));
}

// ============================================================================
// KGEMM v6 (fp16 2-term): u = (ah+al) @ wh.  CTA 256m x 128n, 512 thr
//   (16 warps 4m x 4n, warp 64x32), 4-stage cp.async K=32.
//   smem: 4 x (A 16KB + B 8KB) = 96KB.  Fused head epilogue -> g_part.
// ============================================================================
#define STG_B   24576
#define SMEM_KG (4 * STG_B)

__global__ __launch_bounds__(512) void kgemm(const float* __restrict__ w2) {
    extern __shared__ char smem[];
    const uint32_t sb = smem_u32(smem);
    const int tid = threadIdx.x;
    const int lane = tid & 31, w = tid >> 5;
    const int wm = w >> 2, wn = w & 3;          // warp grid 4(m) x 4(n)
    const int bm = blockIdx.x, bn = blockIdx.y;
    const int ti = lane >> 3, r = lane & 7;

    float acc[4][4][4];
#pragma unroll
    for (int i = 0; i < 4; i++)
#pragma unroll
        for (int j = 0; j < 4; j++)
#pragma unroll
            for (int q = 0; q < 4; q++) acc[i][j][q] = 0.f;

    const char* Ab = (const char*)g_A2 + (size_t)bm * 256 * 2048;
    const char* Bb = (const char*)g_Wc + (size_t)bn * 128 * 1024;

    auto stage_load = [&](int s) {
        const int buf = s & 3;
        const int aof = (s < 16) ? s * 32 : 512 + (s - 16) * 32;
        const int bof = (s & 15) * 32;
        const uint32_t dA = sb + buf * STG_B;
        const uint32_t dB = dA + 16384;
#pragma unroll
        for (int h = 0; h < 2; h++) {
            int q = h * 512 + tid;
            int m = q >> 2, kg = q & 3;
            uint32_t off = (uint32_t)((((m >> 3) * 4 + kg) * 8 + (m & 7)) * 16);
            CP_ASYNC16(dA + off, Ab + (size_t)m * 2048 + (size_t)(aof + kg * 8) * 2);
        }
        {
            int n = tid >> 2, kg = tid & 3;
            uint32_t off = (uint32_t)((((n >> 3) * 4 + kg) * 8 + (n & 7)) * 16);
            CP_ASYNC16(dB + off, Bb + (size_t)n * 1024 + (size_t)(bof + kg * 8) * 2);
        }
        CP_COMMIT();
    };

    stage_load(0); stage_load(1); stage_load(2);

    for (int s = 0; s < NSTEP; s++) {
        CP_WAIT(2);
        __syncthreads();
        const uint32_t sA = sb + (s & 3) * STG_B;
        const uint32_t sB = sA + 16384;
#pragma unroll
        for (int kk = 0; kk < 2; kk++) {
            uint32_t af[4][4];
#pragma unroll
            for (int i = 0; i < 4; i++) {
                int m8 = (wm * 4 + i) * 2 + (ti & 1);
                int k8 = kk * 2 + (ti >> 1);
                LDSM4(af[i], sA + (uint32_t)(((m8 * 4 + k8) * 8 + r) * 16));
            }
            uint32_t bf[2][4];
#pragma unroll
            for (int pj = 0; pj < 2; pj++) {
                int n8 = wn * 4 + pj * 2 + (ti >> 1);
                int k8 = kk * 2 + (ti & 1);
                LDSM4(bf[pj], sB + (uint32_t)(((n8 * 4 + k8) * 8 + r) * 16));
            }
#pragma unroll
            for (int i = 0; i < 4; i++)
#pragma unroll
                for (int j = 0; j < 4; j++)
                    MMA_F16(acc[i][j], af[i], &bf[j >> 1][(j & 1) * 2]);
        }
        if (s + 3 < NSTEP) stage_load(s + 3); else CP_COMMIT();
    }
    CP_WAIT(0);
    __syncthreads();

    // ---- fused head partial epilogue (this CTA's 128 cols) ----
    float* vts  = (float*)smem;            // [128][8]  4KB
    float* w2s  = (float*)(smem + 4096);   // [128][4]  2KB
    float* rbuf = (float*)(smem + 8192);   // [32 rows][4 wn][32] 16KB
    for (int idx = tid; idx < 128 * TSTEPS; idx += 512) vts[idx] = g_vt[bn * 1024 + idx];
    if (tid < 512) {
        if (tid < 128 * 4) w2s[tid] = w2[bn * 512 + tid];
    }
    __syncthreads();

#pragma unroll
    for (int i = 0; i < 4; i++) {
#pragma unroll
        for (int half = 0; half < 2; half++) {
            float part[32];
#pragma unroll
            for (int v = 0; v < 32; v++) part[v] = 0.f;
#pragma unroll
            for (int j = 0; j < 4; j++) {
#pragma unroll
                for (int col = 0; col < 2; col++) {
                    const float u = acc[i][j][half * 2 + col];
                    const int nl = wn * 32 + j * 8 + (lane & 3) * 2 + col;
                    const float* vt8 = vts + nl * 8;
                    float4 wv = *(const float4*)(w2s + nl * 4);
#pragma unroll
                    for (int t = 0; t < 8; t++) {
                        float x = u + vt8[t];
                        float h = fmaxf(x, 0.02f * x);
                        part[t * 4 + 0] += h * wv.x;
                        part[t * 4 + 1] += h * wv.y;
                        part[t * 4 + 2] += h * wv.z;
                        part[t * 4 + 3] += h * wv.w;
                    }
                }
            }
#pragma unroll
            for (int o = 1; o <= 2; o <<= 1)
#pragma unroll
                for (int v = 0; v < 32; v++)
                    part[v] += __shfl_xor_sync(0xffffffffu, part[v], o);
            if ((lane & 3) == 0) {
                int row = wm * 8 + (lane >> 2);       // 0..31
                float* d = rbuf + (row * 4 + wn) * 32;
#pragma unroll
                for (int v = 0; v < 32; v++) d[v] = part[v];
            }
            __syncthreads();
#pragma unroll
            for (int sl = 0; sl < 2; sl++) {
                const int slot = sl * 512 + tid;      // 1024 slots
                const int row = slot >> 5, v = slot & 31;
                const float* src = rbuf + row * 128 + v;
                float sum = src[0] + src[32] + src[64] + src[96];
                const int m_g = bm * 256 + (row >> 3) * 64 + i * 16 + half * 8 + (row & 7);
                g_part[((size_t)bn * NPTS + m_g) * 32 + v] = sum;
            }
            __syncthreads();
        }
    }
}

// ============================================================================
// K3c: reduce 4 bn partials + bias + coords -> logitsT / newcT (transposed)
// ============================================================================
__global__ __launch_bounds__(256) void k3c(const float* __restrict__ coords,
                                           const float* __restrict__ b2) {
    __shared__ float su[64 * 33];
    const int tid = threadIdx.x;
    const int p0 = blockIdx.x * 64;

    float4 a[2] = {{0, 0, 0, 0}, {0, 0, 0, 0}};
#pragma unroll
    for (int bn = 0; bn < 4; bn++) {
#pragma unroll
        for (int it = 0; it < 2; it++) {
            int f = it * 256 + tid;                 // 512 float4 per block
            const float4 v = *(const float4*)(g_part +
                (((size_t)bn * NPTS + p0 + (f >> 3)) * 32 + (f & 7) * 4));
            a[it].x += v.x; a[it].y += v.y; a[it].z += v.z; a[it].w += v.w;
        }
    }
#pragma unroll
    for (int it = 0; it < 2; it++) {
        int f = it * 256 + tid;
        int p = f >> 3, v4 = f & 7;
        float* d = su + p * 33 + v4 * 4;
        d[0] = a[it].x; d[1] = a[it].y; d[2] = a[it].z; d[3] = a[it].w;
    }
    __syncthreads();
    const float b2v[4] = {b2[0], b2[1], b2[2], b2[3]};
#pragma unroll
    for (int it = 0; it < 8; it++) {
        int s = it * 256 + tid;                     // 2048 slots
        int v = s >> 6, pl = s & 63;
        int t = v >> 2, c = v & 3;
        int p = p0 + pl;
        float val = su[pl * 33 + v];
        if (c == 0)
            g_logitsT[t * NPTS + p] = val + b2v[0];
        else
            g_newcT[(t * 3 + c - 1) * NPTS + p] = val + b2v[c] + coords[p * 3 + c - 1];
    }
}

// ============================================================================
// K4: per (segment, t): stable softmax + weighted coord sum -> out[0:384]
// ============================================================================
__global__ __launch_bounds__(512) void k4_soft(const int* __restrict__ np,
                                               float* __restrict__ out) {
    const int b = blockIdx.x >> 3, t = blockIdx.x & 7;
    const int tid = threadIdx.x, lane = tid & 31, warp = tid >> 5;
    int start = 0;
    for (int i = 0; i < b; i++) start += np[i];
    const int end = start + np[b];
    const float* lg = g_logitsT + (size_t)t * NPTS;
    const float* nx = g_newcT + (size_t)(t * 3 + 0) * NPTS;
    const float* ny = g_newcT + (size_t)(t * 3 + 1) * NPTS;
    const float* nz = g_newcT + (size_t)(t * 3 + 2) * NPTS;

    __shared__ float sred[16][4];
    __shared__ float mshared;

    float m = -1e30f;
    for (int p = start + tid; p < end; p += 512) m = fmaxf(m, lg[p]);
#pragma unroll
    for (int o = 16; o > 0; o >>= 1) m = fmaxf(m, __shfl_down_sync(0xffffffffu, m, o));
    if (lane == 0) sred[warp][0] = m;
    __syncthreads();
    if (tid == 0) {
        float v = sred[0][0];
        for (int i = 1; i < 16; i++) v = fmaxf(v, sred[i][0]);
        mshared = v;
    }
    __syncthreads();
    const float mx = mshared;

    float s = 0.f, sx = 0.f, sy = 0.f, sz = 0.f;
    for (int p = start + tid; p < end; p += 512) {
        float e = expf(lg[p] - mx);
        s += e; sx += e * nx[p]; sy += e * ny[p]; sz += e * nz[p];
    }
#pragma unroll
    for (int o = 16; o > 0; o >>= 1) {
        s  += __shfl_down_sync(0xffffffffu, s,  o);
        sx += __shfl_down_sync(0xffffffffu, sx, o);
        sy += __shfl_down_sync(0xffffffffu, sy, o);
        sz += __shfl_down_sync(0xffffffffu, sz, o);
    }
    if (lane == 0) { sred[warp][0] = s; sred[warp][1] = sx; sred[warp][2] = sy; sred[warp][3] = sz; }
    __syncthreads();
    if (tid == 0) {
        float ts = 0, tx = 0, ty = 0, tz = 0;
        for (int i = 0; i < 16; i++) { ts += sred[i][0]; tx += sred[i][1]; ty += sred[i][2]; tz += sred[i][3]; }
        float inv = 1.f / ts;
        out[(b * 8 + t) * 3 + 0] = tx * inv;
        out[(b * 8 + t) * 3 + 1] = ty * inv;
        out[(b * 8 + t) * 3 + 2] = tz * inv;
    }
}

// ============================================================================
// K6: act MLP per (b,t), 512 thr, k-split layer1, uniform barriers
// ============================================================================
__global__ __launch_bounds__(512) void k6_act(const float* __restrict__ traj,
                                              const float* __restrict__ w1,
                                              const float* __restrict__ b1,
                                              const float* __restrict__ w2,
                                              const float* __restrict__ b2,
                                              float* __restrict__ out) {
    __shared__ float row[HID + EMB];
    __shared__ float hid[HID];
    __shared__ float sbuf[4][128][4];
    __shared__ float sred2[OUTC];
    const int bt = blockIdx.x;
    const int b = bt >> 3, t = bt & 7;
    const int tid = threadIdx.x;

    if (tid < HID) {
        float m = -1e30f;
#pragma unroll
        for (int c = 0; c < NCHUNK5; c++) m = fmaxf(m, g_pp[(b * NCHUNK5 + c) * HID + tid]);
        row[tid] = m;
    }
    if (tid < EMB) row[HID + tid] = traj[t * EMB + tid];
    __syncthreads();

    {
        const int jq = tid & 127, kh = tid >> 7;
        const int k0 = kh * 144, k1 = k0 + 144;
        float4 a = {0.f, 0.f, 0.f, 0.f};
#pragma unroll 4
        for (int k = k0; k < k1; k++) {
            float f = row[k];
            float4 wv = *(const float4*)(w1 + (size_t)k * HID + jq * 4);
            a.x += f * wv.x; a.y += f * wv.y; a.z += f * wv.z; a.w += f * wv.w;
        }
        sbuf[kh][jq][0] = a.x; sbuf[kh][jq][1] = a.y;
        sbuf[kh][jq][2] = a.z; sbuf[kh][jq][3] = a.w;
    }
    __syncthreads();
    if (tid < 128) {
#pragma unroll
        for (int c = 0; c < 4; c++) {
            int j = tid * 4 + c;
            float v = sbuf[0][tid][c] + sbuf[1][tid][c] + sbuf[2][tid][c] + sbuf[3][tid][c] + b1[j];
            hid[j] = v >= 0.f ? v : 0.02f * v;
        }
    }
    __syncthreads();

    const bool active = (tid < 2 * OUTC);
    const int h = active ? (tid >= OUTC ? 1 : 0) : 0;
    const int o = active ? (tid - h * OUTC) : 0;
    float a = 0.f;
    if (active) {
        const int k0 = h * 256, k1 = k0 + 256;
#pragma unroll 4
        for (int k = k0; k < k1; k++) a += hid[k] * w2[(size_t)k * OUTC + o];
        if (h) sred2[o] = a;
    }
    __syncthreads();
    if (active && !h) {
        float tot = a + sred2[o] + b2[o];
        const int XT = BATCH * TSTEPS * 3;
        const int XR = BATCH * TSTEPS * 216;
        if (o < 216)       out[XT + bt * 216 + o] = tot;
        else if (o == 216) out[XT + XR + bt] = tot;
        else               out[XT + XR + BATCH * TSTEPS + bt] = tot;
    }
}

// ============================================================================
extern "C" void kernel_launch(void* const* d_in, const int* in_sizes, int n_in,
                              void* d_out, int out_size) {
    const float* pe     = (const float*)d_in[0];
    const float* coords = (const float*)d_in[1];
    const float* traj   = (const float*)d_in[2];
    const float* hw1    = (const float*)d_in[3];
    const float* hb1    = (const float*)d_in[4];
    const float* hw2    = (const float*)d_in[5];
    const float* hb2    = (const float*)d_in[6];
    const float* aw1    = (const float*)d_in[7];
    const float* ab1    = (const float*)d_in[8];
    const float* aw2    = (const float*)d_in[9];
    const float* ab2    = (const float*)d_in[10];
    const int*   np     = (const int*)d_in[11];
    float* out = (float*)d_out;

    static bool attr_set = false;
    if (!attr_set) {
        cudaFuncSetAttribute(kgemm, cudaFuncAttributeMaxDynamicSharedMemorySize, SMEM_KG);
        attr_set = true;
    }

    k0a_conv<<<NPTS * 64 / 256, 256>>>(pe);                          // 1
    k0w_conv<<<dim3(16, 17), dim3(32, 8)>>>(hw1, hb1, traj);         // 2
    k5a<<<dim3(BATCH, HID / 128, NCHUNK5), 128>>>(pe, np);           // 3
    kgemm<<<dim3(NPTS / 256, 4), 512, SMEM_KG>>>(hw2);               // 4 (profiled)
    k3c<<<NPTS / 64, 256>>>(coords, hb2);                            // 5
    k4_soft<<<BATCH * TSTEPS, 512>>>(np, out);                       // 6
    k6_act<<<BATCH * TSTEPS, 512>>>(traj, aw1, ab1, aw2, ab2, out);  // 7
}

// round 10
// speedup vs baseline: 3.7521x; 1.3845x over previous
#include <cuda_runtime.h>
#include <cuda_fp16.h>
#include <cstdint>

#define NPTS    16384
#define BATCH   16
#define HID     512
#define EMB     64
#define TSTEPS  8
#define OUTC    218
#define NSTEP   16           // K = 512 (fp16 single-term) in 32-wide k-steps
#define NCHUNK5 16

// ---- scratch (static device allocations) ----
__device__ __align__(128) __half g_A[NPTS * 512];    // ah per row (16 MB)
__device__ __align__(128) __half g_Wc[HID * 512];    // wh, [n][k] K contig
__device__ float g_vt[HID * TSTEPS];          // [j][t]
__device__ float g_part[4 * NPTS * 32];       // [bn][p][t*4+c] head partials (8 MB)
__device__ float g_pp[BATCH * NCHUNK5 * HID];

// ============================ PTX helpers ====================================
__device__ __forceinline__ uint32_t smem_u32(const void* p) {
    uint32_t a;
    asm("{ .reg .u64 t; cvta.to.shared.u64 t, %1; cvt.u32.u64 %0, t; }" : "=r"(a) : "l"(p));
    return a;
}
#define CP_ASYNC16(dst, src) \
    asm volatile("cp.async.cg.shared.global [%0], [%1], 16;" :: "r"(dst), "l"(src) : "memory")
#define CP_COMMIT() asm volatile("cp.async.commit_group;" ::: "memory")
#define CP_WAIT(n)  asm volatile("cp.async.wait_group %0;" :: "n"(n) : "memory")

#define LDSM4(d, a) \
    asm volatile("ldmatrix.sync.aligned.m8n8.x4.shared.b16 {%0,%1,%2,%3}, [%4];" \
                 : "=r"((d)[0]), "=r"((d)[1]), "=r"((d)[2]), "=r"((d)[3]) : "r"(a))

#define MMA_F16(c, a, b) \
    asm volatile( \
        "mma.sync.aligned.m16n8k16.row.col.f32.f16.f16.f32 " \
        "{%0,%1,%2,%3},{%4,%5,%6,%7},{%8,%9},{%0,%1,%2,%3};" \
        : "+f"((c)[0]), "+f"((c)[1]), "+f"((c)[2]), "+f"((c)[3]) \
        : "r"((a)[0]), "r"((a)[1]), "r"((a)[2]), "r"((a)[3]), "r"((b)[0]), "r"((b)[1]))

// ============================================================================
// KPRE: merged preprocessing, grid-partitioned.
//   [0, 4096):      point_embeds fp32 -> fp16 into g_A
//   [4096, 4368):   (y<16) transpose hm_w1[:512] -> g_Wc; (y==16) vt compute
//   [4368, 4880):   segment max-pool phase 1 -> g_pp
// ============================================================================
__global__ __launch_bounds__(256) void kpre(const float* __restrict__ pe,
                                            const float* __restrict__ w1,
                                            const float* __restrict__ b1,
                                            const float* __restrict__ traj,
                                            const int* __restrict__ np) {
    __shared__ float s[32][33];
    const int bid = blockIdx.x, tid = threadIdx.x;

    if (bid < 4096) {
        int idx = bid * 256 + tid;
        int row = idx >> 6, g = idx & 63;
        const float* src = pe + (size_t)row * HID + g * 8;
        float4 f0 = *(const float4*)src;
        float4 f1 = *(const float4*)(src + 4);
        float f[8] = {f0.x, f0.y, f0.z, f0.w, f1.x, f1.y, f1.z, f1.w};
        __align__(16) __half hi[8];
#pragma unroll
        for (int i = 0; i < 8; i++) hi[i] = __float2half_rn(f[i]);
        *(uint4*)(g_A + (size_t)row * 512 + g * 8) = *(const uint4*)hi;
    } else if (bid < 4368) {
        const int id = bid - 4096;
        const int x = id & 15, y = id >> 4;       // y: 0..16
        const int tx = tid & 31, ty = tid >> 5;
        if (y == 16) {
            const int j = x * 32 + tx;
            const int t = ty;
            float acc = b1[j];
#pragma unroll 8
            for (int e = 0; e < EMB; e++)
                acc += traj[t * EMB + e] * w1[(size_t)(HID + e) * HID + j];
            g_vt[j * TSTEPS + t] = acc;
            return;
        }
        const int kb = y * 32, nb = x * 32;
#pragma unroll
        for (int i = 0; i < 4; i++) {
            int k = ty + i * 8;
            s[k][tx] = w1[(size_t)(kb + k) * HID + nb + tx];
        }
        __syncthreads();
#pragma unroll
        for (int i = 0; i < 4; i++) {
            int nr = ty + i * 8;
            g_Wc[(size_t)(nb + nr) * 512 + kb + tx] = __float2half_rn(s[tx][nr]);
        }
    } else {
        const int id = bid - 4368;
        const int b = id & 15, colh = (id >> 4) & 1, chunk = id >> 5;
        const int col = colh * 256 + tid;
        int start = 0;
        for (int i = 0; i < b; i++) start += np[i];
        const int len = np[b];
        const int c0 = start + (chunk * len) / NCHUNK5;
        const int c1 = start + ((chunk + 1) * len) / NCHUNK5;
        float m0 = -1e30f, m1 = -1e30f, m2 = -1e30f, m3 = -1e30f;
        int p = c0;
        for (; p + 3 < c1; p += 4) {
            m0 = fmaxf(m0, pe[(size_t)p * HID + col]);
            m1 = fmaxf(m1, pe[(size_t)(p + 1) * HID + col]);
            m2 = fmaxf(m2, pe[(size_t)(p + 2) * HID + col]);
            m3 = fmaxf(m3, pe[(size_t)(p + 3) * HID + col]);
        }
        for (; p < c1; p++) m0 = fmaxf(m0, pe[(size_t)p * HID + col]);
        g_pp[(b * NCHUNK5 + chunk) * HID + col] = fmaxf(fmaxf(m0, m1), fmaxf(m2, m3));
    }
}

// ============================================================================
// KGEMM v7 (fp16 single-term): u = ah @ wh, K = 512.  CTA 256m x 128n,
//   512 thr (16 warps 4m x 4n, warp 64x32), 6-stage cp.async K=32.
//   smem: 6 x (A 16KB + B 8KB) = 144KB.  Fused head epilogue -> g_part.
// ============================================================================
#define STG_B   24576
#define SMEM_KG (6 * STG_B)

__global__ __launch_bounds__(512) void kgemm(const float* __restrict__ w2) {
    extern __shared__ char smem[];
    const uint32_t sb = smem_u32(smem);
    const int tid = threadIdx.x;
    const int lane = tid & 31, w = tid >> 5;
    const int wm = w >> 2, wn = w & 3;          // warp grid 4(m) x 4(n)
    const int bm = blockIdx.x, bn = blockIdx.y;
    const int ti = lane >> 3, r = lane & 7;

    float acc[4][4][4];
#pragma unroll
    for (int i = 0; i < 4; i++)
#pragma unroll
        for (int j = 0; j < 4; j++)
#pragma unroll
            for (int q = 0; q < 4; q++) acc[i][j][q] = 0.f;

    const char* Ab = (const char*)g_A + (size_t)bm * 256 * 1024;
    const char* Bb = (const char*)g_Wc + (size_t)bn * 128 * 1024;

    auto stage_load = [&](int s) {
        const int buf = s % 6;
        const int kof = s * 32;
        const uint32_t dA = sb + buf * STG_B;
        const uint32_t dB = dA + 16384;
#pragma unroll
        for (int h = 0; h < 2; h++) {
            int q = h * 512 + tid;
            int m = q >> 2, kg = q & 3;
            uint32_t off = (uint32_t)((((m >> 3) * 4 + kg) * 8 + (m & 7)) * 16);
            CP_ASYNC16(dA + off, Ab + (size_t)m * 1024 + (size_t)(kof + kg * 8) * 2);
        }
        {
            int n = tid >> 2, kg = tid & 3;
            uint32_t off = (uint32_t)((((n >> 3) * 4 + kg) * 8 + (n & 7)) * 16);
            CP_ASYNC16(dB + off, Bb + (size_t)n * 1024 + (size_t)(kof + kg * 8) * 2);
        }
        CP_COMMIT();
    };

    stage_load(0); stage_load(1); stage_load(2); stage_load(3); stage_load(4);

    for (int s = 0; s < NSTEP; s++) {
        CP_WAIT(4);
        __syncthreads();
        const uint32_t sA = sb + (s % 6) * STG_B;
        const uint32_t sB = sA + 16384;
#pragma unroll
        for (int kk = 0; kk < 2; kk++) {
            uint32_t af[4][4];
#pragma unroll
            for (int i = 0; i < 4; i++) {
                int m8 = (wm * 4 + i) * 2 + (ti & 1);
                int k8 = kk * 2 + (ti >> 1);
                LDSM4(af[i], sA + (uint32_t)(((m8 * 4 + k8) * 8 + r) * 16));
            }
            uint32_t bf[2][4];
#pragma unroll
            for (int pj = 0; pj < 2; pj++) {
                int n8 = wn * 4 + pj * 2 + (ti >> 1);
                int k8 = kk * 2 + (ti & 1);
                LDSM4(bf[pj], sB + (uint32_t)(((n8 * 4 + k8) * 8 + r) * 16));
            }
#pragma unroll
            for (int i = 0; i < 4; i++)
#pragma unroll
                for (int j = 0; j < 4; j++)
                    MMA_F16(acc[i][j], af[i], &bf[j >> 1][(j & 1) * 2]);
        }
        if (s + 5 < NSTEP) stage_load(s + 5); else CP_COMMIT();
    }
    CP_WAIT(0);
    __syncthreads();

    // ---- fused head partial epilogue (this CTA's 128 cols) ----
    float* vts  = (float*)smem;            // [128][8]  4KB
    float* w2s  = (float*)(smem + 4096);   // [128][4]  2KB
    float* rbuf = (float*)(smem + 8192);   // [32 rows][4 wn][32] 16KB
    for (int idx = tid; idx < 128 * TSTEPS; idx += 512) vts[idx] = g_vt[bn * 1024 + idx];
    if (tid < 128 * 4) w2s[tid] = w2[bn * 512 + tid];
    __syncthreads();

#pragma unroll
    for (int i = 0; i < 4; i++) {
#pragma unroll
        for (int half = 0; half < 2; half++) {
            float part[32];
#pragma unroll
            for (int v = 0; v < 32; v++) part[v] = 0.f;
#pragma unroll
            for (int j = 0; j < 4; j++) {
#pragma unroll
                for (int col = 0; col < 2; col++) {
                    const float u = acc[i][j][half * 2 + col];
                    const int nl = wn * 32 + j * 8 + (lane & 3) * 2 + col;
                    const float* vt8 = vts + nl * 8;
                    float4 wv = *(const float4*)(w2s + nl * 4);
#pragma unroll
                    for (int t = 0; t < 8; t++) {
                        float x = u + vt8[t];
                        float h = fmaxf(x, 0.02f * x);
                        part[t * 4 + 0] += h * wv.x;
                        part[t * 4 + 1] += h * wv.y;
                        part[t * 4 + 2] += h * wv.z;
                        part[t * 4 + 3] += h * wv.w;
                    }
                }
            }
#pragma unroll
            for (int o = 1; o <= 2; o <<= 1)
#pragma unroll
                for (int v = 0; v < 32; v++)
                    part[v] += __shfl_xor_sync(0xffffffffu, part[v], o);
            if ((lane & 3) == 0) {
                int row = wm * 8 + (lane >> 2);       // 0..31
                float* d = rbuf + (row * 4 + wn) * 32;
#pragma unroll
                for (int v = 0; v < 32; v++) d[v] = part[v];
            }
            __syncthreads();
#pragma unroll
            for (int sl = 0; sl < 2; sl++) {
                const int slot = sl * 512 + tid;      // 1024 slots
                const int row = slot >> 5, v = slot & 31;
                const float* src = rbuf + row * 128 + v;
                float sum = src[0] + src[32] + src[64] + src[96];
                const int m_g = bm * 256 + (row >> 3) * 64 + i * 16 + half * 8 + (row & 7);
                g_part[((size_t)bn * NPTS + m_g) * 32 + v] = sum;
            }
            __syncthreads();
        }
    }
}

// ============================================================================
// K4 (k3c fused in): per (segment, t) softmax + weighted coord sum from g_part.
//   logit = sum_bn part[bn][p][t*4]   (b2[0] cancels in softmax)
//   newc_c = coords[p][c] + sum_bn part[..][t*4+1+c] + b2[1+c]
// ============================================================================
__global__ __launch_bounds__(512) void k4_soft(const int* __restrict__ np,
                                               const float* __restrict__ coords,
                                               const float* __restrict__ b2,
                                               float* __restrict__ out) {
    const int b = blockIdx.x >> 3, t = blockIdx.x & 7;
    const int tid = threadIdx.x, lane = tid & 31, warp = tid >> 5;
    int start = 0;
    for (int i = 0; i < b; i++) start += np[i];
    const int end = start + np[b];

    __shared__ float sred[16][4];
    __shared__ float mshared;

    // pass 1: max logit
    float m = -1e30f;
    for (int p = start + tid; p < end; p += 512) {
        float l = g_part[(size_t)p * 32 + t * 4]
                + g_part[((size_t)NPTS + p) * 32 + t * 4]
                + g_part[((size_t)2 * NPTS + p) * 32 + t * 4]
                + g_part[((size_t)3 * NPTS + p) * 32 + t * 4];
        m = fmaxf(m, l);
    }
#pragma unroll
    for (int o = 16; o > 0; o >>= 1) m = fmaxf(m, __shfl_down_sync(0xffffffffu, m, o));
    if (lane == 0) sred[warp][0] = m;
    __syncthreads();
    if (tid == 0) {
        float v = sred[0][0];
        for (int i = 1; i < 16; i++) v = fmaxf(v, sred[i][0]);
        mshared = v;
    }
    __syncthreads();
    const float mx = mshared;
    const float b2x = b2[1], b2y = b2[2], b2z = b2[3];

    // pass 2: exp-weighted sums
    float s = 0.f, sx = 0.f, sy = 0.f, sz = 0.f;
    for (int p = start + tid; p < end; p += 512) {
        float4 v0 = *(const float4*)(g_part + (size_t)p * 32 + t * 4);
        float4 v1 = *(const float4*)(g_part + ((size_t)NPTS + p) * 32 + t * 4);
        float4 v2 = *(const float4*)(g_part + ((size_t)2 * NPTS + p) * 32 + t * 4);
        float4 v3 = *(const float4*)(g_part + ((size_t)3 * NPTS + p) * 32 + t * 4);
        float l  = v0.x + v1.x + v2.x + v3.x;
        float dx = v0.y + v1.y + v2.y + v3.y;
        float dy = v0.z + v1.z + v2.z + v3.z;
        float dz = v0.w + v1.w + v2.w + v3.w;
        float e = expf(l - mx);
        s  += e;
        sx += e * (coords[p * 3 + 0] + dx + b2x);
        sy += e * (coords[p * 3 + 1] + dy + b2y);
        sz += e * (coords[p * 3 + 2] + dz + b2z);
    }
#pragma unroll
    for (int o = 16; o > 0; o >>= 1) {
        s  += __shfl_down_sync(0xffffffffu, s,  o);
        sx += __shfl_down_sync(0xffffffffu, sx, o);
        sy += __shfl_down_sync(0xffffffffu, sy, o);
        sz += __shfl_down_sync(0xffffffffu, sz, o);
    }
    if (lane == 0) { sred[warp][0] = s; sred[warp][1] = sx; sred[warp][2] = sy; sred[warp][3] = sz; }
    __syncthreads();
    if (tid == 0) {
        float ts = 0, tx = 0, ty = 0, tz = 0;
        for (int i = 0; i < 16; i++) { ts += sred[i][0]; tx += sred[i][1]; ty += sred[i][2]; tz += sred[i][3]; }
        float inv = 1.f / ts;
        out[(b * 8 + t) * 3 + 0] = tx * inv;
        out[(b * 8 + t) * 3 + 1] = ty * inv;
        out[(b * 8 + t) * 3 + 2] = tz * inv;
    }
}

// ============================================================================
// K6: act MLP, 64 blocks x 2 (b,t) rows/block sharing weight loads, 512 thr
// ============================================================================
__global__ __launch_bounds__(512) void k6_act(const float* __restrict__ traj,
                                              const float* __restrict__ w1,
                                              const float* __restrict__ b1,
                                              const float* __restrict__ w2,
                                              const float* __restrict__ b2,
                                              float* __restrict__ out) {
    __shared__ float rows[2][HID + EMB];
    __shared__ float hid[2][HID];
    __shared__ float sbuf[2][4][128][4];
    __shared__ float sred2[2][OUTC];
    const int b = blockIdx.x >> 2, tp = blockIdx.x & 3;
    const int t0 = tp * 2;
    const int tid = threadIdx.x;

    if (tid < HID) {
        float m = -1e30f;
#pragma unroll
        for (int c = 0; c < NCHUNK5; c++) m = fmaxf(m, g_pp[(b * NCHUNK5 + c) * HID + tid]);
        rows[0][tid] = m;
        rows[1][tid] = m;
    }
    if (tid < 2 * EMB) {
        int rr = tid >> 6, e = tid & 63;
        rows[rr][HID + e] = traj[(t0 + rr) * EMB + e];
    }
    __syncthreads();

    // layer 1: 4-way k split, float4 over j, both rows per weight load
    {
        const int jq = tid & 127, kh = tid >> 7;
        const int k0 = kh * 144, k1 = k0 + 144;
        float4 a0 = {0.f, 0.f, 0.f, 0.f}, a1 = {0.f, 0.f, 0.f, 0.f};
#pragma unroll 4
        for (int k = k0; k < k1; k++) {
            float4 wv = *(const float4*)(w1 + (size_t)k * HID + jq * 4);
            float f0 = rows[0][k], f1 = rows[1][k];
            a0.x += f0 * wv.x; a0.y += f0 * wv.y; a0.z += f0 * wv.z; a0.w += f0 * wv.w;
            a1.x += f1 * wv.x; a1.y += f1 * wv.y; a1.z += f1 * wv.z; a1.w += f1 * wv.w;
        }
        sbuf[0][kh][jq][0] = a0.x; sbuf[0][kh][jq][1] = a0.y;
        sbuf[0][kh][jq][2] = a0.z; sbuf[0][kh][jq][3] = a0.w;
        sbuf[1][kh][jq][0] = a1.x; sbuf[1][kh][jq][1] = a1.y;
        sbuf[1][kh][jq][2] = a1.z; sbuf[1][kh][jq][3] = a1.w;
    }
    __syncthreads();
    if (tid < 256) {
        const int rr = tid >> 7, jj = tid & 127;
#pragma unroll
        for (int c = 0; c < 4; c++) {
            int j = jj * 4 + c;
            float v = sbuf[rr][0][jj][c] + sbuf[rr][1][jj][c] +
                      sbuf[rr][2][jj][c] + sbuf[rr][3][jj][c] + b1[j];
            hid[rr][j] = v >= 0.f ? v : 0.02f * v;
        }
    }
    __syncthreads();

    // layer 2: 2-way k split over 218 outputs, both rows per weight load
    const bool active = (tid < 2 * OUTC);
    const int h = active ? (tid >= OUTC ? 1 : 0) : 0;
    const int o = active ? (tid - h * OUTC) : 0;
    float a0 = 0.f, a1 = 0.f;
    if (active) {
        const int k0 = h * 256, k1 = k0 + 256;
#pragma unroll 4
        for (int k = k0; k < k1; k++) {
            float wv = w2[(size_t)k * OUTC + o];
            a0 += hid[0][k] * wv;
            a1 += hid[1][k] * wv;
        }
        if (h) { sred2[0][o] = a0; sred2[1][o] = a1; }
    }
    __syncthreads();
    if (active && !h) {
        const int XT = BATCH * TSTEPS * 3;
        const int XR = BATCH * TSTEPS * 216;
        const float bias = b2[o];
#pragma unroll
        for (int rr = 0; rr < 2; rr++) {
            float tot = (rr ? a1 : a0) + sred2[rr][o] + bias;
            const int bt = b * 8 + t0 + rr;
            if (o < 216)       out[XT + bt * 216 + o] = tot;
            else if (o == 216) out[XT + XR + bt] = tot;
            else               out[XT + XR + BATCH * TSTEPS + bt] = tot;
        }
    }
}

// ============================================================================
extern "C" void kernel_launch(void* const* d_in, const int* in_sizes, int n_in,
                              void* d_out, int out_size) {
    const float* pe     = (const float*)d_in[0];
    const float* coords = (const float*)d_in[1];
    const float* traj   = (const float*)d_in[2];
    const float* hw1    = (const float*)d_in[3];
    const float* hb1    = (const float*)d_in[4];
    const float* hw2    = (const float*)d_in[5];
    const float* hb2    = (const float*)d_in[6];
    const float* aw1    = (const float*)d_in[7];
    const float* ab1    = (const float*)d_in[8];
    const float* aw2    = (const float*)d_in[9];
    const float* ab2    = (const float*)d_in[10];
    const int*   np     = (const int*)d_in[11];
    float* out = (float*)d_out;

    static bool attr_set = false;
    if (!attr_set) {
        cudaFuncSetAttribute(kgemm, cudaFuncAttributeMaxDynamicSharedMemorySize, SMEM_KG);
        attr_set = true;
    }

    kpre<<<4880, 256>>>(pe, hw1, hb1, traj, np);                     // 1
    kgemm<<<dim3(NPTS / 256, 4), 512, SMEM_KG>>>(hw2);               // 2 (profiled)
    k4_soft<<<BATCH * TSTEPS, 512>>>(np, coords, hb2, out);          // 3
    k6_act<<<BATCH * TSTEPS / 2, 512>>>(traj, aw1, ab1, aw2, ab2, out); // 4
}

// round 11
// speedup vs baseline: 4.2633x; 1.1363x over previous
#include <cuda_runtime.h>
#include <cuda_fp16.h>
#include <cstdint>

#define NPTS    16384
#define BATCH   16
#define HID     512
#define EMB     64
#define TSTEPS  8
#define OUTC    218
#define NSTEP   16           // K = 512 (fp16 single-term) in 32-wide k-steps
#define NCHUNK5 16

// ---- scratch (static device allocations) ----
__device__ __align__(128) __half g_A[NPTS * 512];    // ah per row (16 MB)
__device__ __align__(128) __half g_Wc[HID * 512];    // wh, [n][k] K contig
__device__ float g_vt[HID * TSTEPS];          // heatmap vt [j][t]
__device__ float g_part[4 * NPTS * 32];       // [bn][p][t*4+c] head partials (8 MB)
__device__ float g_pp[BATCH * NCHUNK5 * HID];
__device__ float g_base4[4][BATCH][HID];      // act layer-1 partials (k-split 4)
__device__ float g_tv[TSTEPS][HID];           // act traj part + b1
__device__ __align__(16) float g_w2T[OUTC * HID];  // act_w2 transposed [o][k]

// ============================ PTX helpers ====================================
__device__ __forceinline__ uint32_t smem_u32(const void* p) {
    uint32_t a;
    asm("{ .reg .u64 t; cvta.to.shared.u64 t, %1; cvt.u32.u64 %0, t; }" : "=r"(a) : "l"(p));
    return a;
}
#define CP_ASYNC16(dst, src) \
    asm volatile("cp.async.cg.shared.global [%0], [%1], 16;" :: "r"(dst), "l"(src) : "memory")
#define CP_COMMIT() asm volatile("cp.async.commit_group;" ::: "memory")
#define CP_WAIT(n)  asm volatile("cp.async.wait_group %0;" :: "n"(n) : "memory")

#define LDSM4(d, a) \
    asm volatile("ldmatrix.sync.aligned.m8n8.x4.shared.b16 {%0,%1,%2,%3}, [%4];" \
                 : "=r"((d)[0]), "=r"((d)[1]), "=r"((d)[2]), "=r"((d)[3]) : "r"(a))

#define MMA_F16(c, a, b) \
    asm volatile( \
        "mma.sync.aligned.m16n8k16.row.col.f32.f16.f16.f32 " \
        "{%0,%1,%2,%3},{%4,%5,%6,%7},{%8,%9},{%0,%1,%2,%3};" \
        : "+f"((c)[0]), "+f"((c)[1]), "+f"((c)[2]), "+f"((c)[3]) \
        : "r"((a)[0]), "r"((a)[1]), "r"((a)[2]), "r"((a)[3]), "r"((b)[0]), "r"((b)[1]))

// ============================================================================
// KPRE: merged preprocessing, grid-partitioned.
//   [0, 4096):      point_embeds fp32 -> fp16 into g_A
//   [4096, 4368):   (y<16) transpose hm_w1[:512] -> g_Wc; (y==16) heatmap vt
//   [4368, 4880):   segment max-pool phase 1 -> g_pp
//   [4880, 4992):   transpose act_w2 -> g_w2T [o][k]
// ============================================================================
__global__ __launch_bounds__(256) void kpre(const float* __restrict__ pe,
                                            const float* __restrict__ w1,
                                            const float* __restrict__ b1,
                                            const float* __restrict__ traj,
                                            const int* __restrict__ np,
                                            const float* __restrict__ aw2) {
    __shared__ float s[32][33];
    const int bid = blockIdx.x, tid = threadIdx.x;

    if (bid < 4096) {
        int idx = bid * 256 + tid;
        int row = idx >> 6, g = idx & 63;
        const float* src = pe + (size_t)row * HID + g * 8;
        float4 f0 = *(const float4*)src;
        float4 f1 = *(const float4*)(src + 4);
        float f[8] = {f0.x, f0.y, f0.z, f0.w, f1.x, f1.y, f1.z, f1.w};
        __align__(16) __half hi[8];
#pragma unroll
        for (int i = 0; i < 8; i++) hi[i] = __float2half_rn(f[i]);
        *(uint4*)(g_A + (size_t)row * 512 + g * 8) = *(const uint4*)hi;
    } else if (bid < 4368) {
        const int id = bid - 4096;
        const int x = id & 15, y = id >> 4;       // y: 0..16
        const int tx = tid & 31, ty = tid >> 5;
        if (y == 16) {
            const int j = x * 32 + tx;
            const int t = ty;
            float acc = b1[j];
#pragma unroll 8
            for (int e = 0; e < EMB; e++)
                acc += traj[t * EMB + e] * w1[(size_t)(HID + e) * HID + j];
            g_vt[j * TSTEPS + t] = acc;
            return;
        }
        const int kb = y * 32, nb = x * 32;
#pragma unroll
        for (int i = 0; i < 4; i++) {
            int k = ty + i * 8;
            s[k][tx] = w1[(size_t)(kb + k) * HID + nb + tx];
        }
        __syncthreads();
#pragma unroll
        for (int i = 0; i < 4; i++) {
            int nr = ty + i * 8;
            g_Wc[(size_t)(nb + nr) * 512 + kb + tx] = __float2half_rn(s[tx][nr]);
        }
    } else if (bid < 4880) {
        const int id = bid - 4368;
        const int b = id & 15, colh = (id >> 4) & 1, chunk = id >> 5;
        const int col = colh * 256 + tid;
        int start = 0;
        for (int i = 0; i < b; i++) start += np[i];
        const int len = np[b];
        const int c0 = start + (chunk * len) / NCHUNK5;
        const int c1 = start + ((chunk + 1) * len) / NCHUNK5;
        float m0 = -1e30f, m1 = -1e30f, m2 = -1e30f, m3 = -1e30f;
        int p = c0;
        for (; p + 3 < c1; p += 4) {
            m0 = fmaxf(m0, pe[(size_t)p * HID + col]);
            m1 = fmaxf(m1, pe[(size_t)(p + 1) * HID + col]);
            m2 = fmaxf(m2, pe[(size_t)(p + 2) * HID + col]);
            m3 = fmaxf(m3, pe[(size_t)(p + 3) * HID + col]);
        }
        for (; p < c1; p++) m0 = fmaxf(m0, pe[(size_t)p * HID + col]);
        g_pp[(b * NCHUNK5 + chunk) * HID + col] = fmaxf(fmaxf(m0, m1), fmaxf(m2, m3));
    } else {
        // transpose act_w2 [k=512][o=218] -> g_w2T [o][k]
        const int id = bid - 4880;
        const int ox = id % 7, ky = id / 7;       // 7 x 16 tiles
        const int o0 = ox * 32, k0 = ky * 32;
        const int tx = tid & 31, ty = tid >> 5;
#pragma unroll
        for (int i = 0; i < 4; i++) {
            int k = k0 + ty + i * 8;
            int o = o0 + tx;
            s[ty + i * 8][tx] = (o < OUTC) ? aw2[(size_t)k * OUTC + o] : 0.f;
        }
        __syncthreads();
#pragma unroll
        for (int i = 0; i < 4; i++) {
            int o = o0 + ty + i * 8;
            if (o < OUTC) g_w2T[(size_t)o * HID + k0 + tx] = s[tx][ty + i * 8];
        }
    }
}

// ============================================================================
// KGEMM (fp16 single-term): u = ah @ wh, K = 512.  CTA 256m x 128n,
//   512 thr (16 warps 4m x 4n, warp 64x32), 6-stage cp.async K=32.
//   smem: 6 x (A 16KB + B 8KB) = 144KB.  Fused head epilogue -> g_part.
// ============================================================================
#define STG_B   24576
#define SMEM_KG (6 * STG_B)

__global__ __launch_bounds__(512) void kgemm(const float* __restrict__ w2) {
    extern __shared__ char smem[];
    const uint32_t sb = smem_u32(smem);
    const int tid = threadIdx.x;
    const int lane = tid & 31, w = tid >> 5;
    const int wm = w >> 2, wn = w & 3;          // warp grid 4(m) x 4(n)
    const int bm = blockIdx.x, bn = blockIdx.y;
    const int ti = lane >> 3, r = lane & 7;

    float acc[4][4][4];
#pragma unroll
    for (int i = 0; i < 4; i++)
#pragma unroll
        for (int j = 0; j < 4; j++)
#pragma unroll
            for (int q = 0; q < 4; q++) acc[i][j][q] = 0.f;

    const char* Ab = (const char*)g_A + (size_t)bm * 256 * 1024;
    const char* Bb = (const char*)g_Wc + (size_t)bn * 128 * 1024;

    auto stage_load = [&](int s) {
        const int buf = s % 6;
        const int kof = s * 32;
        const uint32_t dA = sb + buf * STG_B;
        const uint32_t dB = dA + 16384;
#pragma unroll
        for (int h = 0; h < 2; h++) {
            int q = h * 512 + tid;
            int m = q >> 2, kg = q & 3;
            uint32_t off = (uint32_t)((((m >> 3) * 4 + kg) * 8 + (m & 7)) * 16);
            CP_ASYNC16(dA + off, Ab + (size_t)m * 1024 + (size_t)(kof + kg * 8) * 2);
        }
        {
            int n = tid >> 2, kg = tid & 3;
            uint32_t off = (uint32_t)((((n >> 3) * 4 + kg) * 8 + (n & 7)) * 16);
            CP_ASYNC16(dB + off, Bb + (size_t)n * 1024 + (size_t)(kof + kg * 8) * 2);
        }
        CP_COMMIT();
    };

    stage_load(0); stage_load(1); stage_load(2); stage_load(3); stage_load(4);

    for (int s = 0; s < NSTEP; s++) {
        CP_WAIT(4);
        __syncthreads();
        const uint32_t sA = sb + (s % 6) * STG_B;
        const uint32_t sB = sA + 16384;
#pragma unroll
        for (int kk = 0; kk < 2; kk++) {
            uint32_t af[4][4];
#pragma unroll
            for (int i = 0; i < 4; i++) {
                int m8 = (wm * 4 + i) * 2 + (ti & 1);
                int k8 = kk * 2 + (ti >> 1);
                LDSM4(af[i], sA + (uint32_t)(((m8 * 4 + k8) * 8 + r) * 16));
            }
            uint32_t bf[2][4];
#pragma unroll
            for (int pj = 0; pj < 2; pj++) {
                int n8 = wn * 4 + pj * 2 + (ti >> 1);
                int k8 = kk * 2 + (ti & 1);
                LDSM4(bf[pj], sB + (uint32_t)(((n8 * 4 + k8) * 8 + r) * 16));
            }
#pragma unroll
            for (int i = 0; i < 4; i++)
#pragma unroll
                for (int j = 0; j < 4; j++)
                    MMA_F16(acc[i][j], af[i], &bf[j >> 1][(j & 1) * 2]);
        }
        if (s + 5 < NSTEP) stage_load(s + 5); else CP_COMMIT();
    }
    CP_WAIT(0);
    __syncthreads();

    // ---- fused head partial epilogue (this CTA's 128 cols) ----
    float* vts  = (float*)smem;            // [128][8]  4KB
    float* w2s  = (float*)(smem + 4096);   // [128][4]  2KB
    float* rbuf = (float*)(smem + 8192);   // [32 rows][4 wn][32] 16KB
    for (int idx = tid; idx < 128 * TSTEPS; idx += 512) vts[idx] = g_vt[bn * 1024 + idx];
    if (tid < 128 * 4) w2s[tid] = w2[bn * 512 + tid];
    __syncthreads();

#pragma unroll
    for (int i = 0; i < 4; i++) {
#pragma unroll
        for (int half = 0; half < 2; half++) {
            float part[32];
#pragma unroll
            for (int v = 0; v < 32; v++) part[v] = 0.f;
#pragma unroll
            for (int j = 0; j < 4; j++) {
#pragma unroll
                for (int col = 0; col < 2; col++) {
                    const float u = acc[i][j][half * 2 + col];
                    const int nl = wn * 32 + j * 8 + (lane & 3) * 2 + col;
                    const float* vt8 = vts + nl * 8;
                    float4 wv = *(const float4*)(w2s + nl * 4);
#pragma unroll
                    for (int t = 0; t < 8; t++) {
                        float x = u + vt8[t];
                        float h = fmaxf(x, 0.02f * x);
                        part[t * 4 + 0] += h * wv.x;
                        part[t * 4 + 1] += h * wv.y;
                        part[t * 4 + 2] += h * wv.z;
                        part[t * 4 + 3] += h * wv.w;
                    }
                }
            }
#pragma unroll
            for (int o = 1; o <= 2; o <<= 1)
#pragma unroll
                for (int v = 0; v < 32; v++)
                    part[v] += __shfl_xor_sync(0xffffffffu, part[v], o);
            if ((lane & 3) == 0) {
                int row = wm * 8 + (lane >> 2);       // 0..31
                float* d = rbuf + (row * 4 + wn) * 32;
#pragma unroll
                for (int v = 0; v < 32; v++) d[v] = part[v];
            }
            __syncthreads();
#pragma unroll
            for (int sl = 0; sl < 2; sl++) {
                const int slot = sl * 512 + tid;      // 1024 slots
                const int row = slot >> 5, v = slot & 31;
                const float* src = rbuf + row * 128 + v;
                float sum = src[0] + src[32] + src[64] + src[96];
                const int m_g = bm * 256 + (row >> 3) * 64 + i * 16 + half * 8 + (row & 7);
                g_part[((size_t)bn * NPTS + m_g) * 32 + v] = sum;
            }
            __syncthreads();
        }
    }
}

// ============================================================================
// K4 (grid-partitioned):
//   [0, 128):   per (b,t) softmax + weighted coord sum -> out[0:384]
//   [128, 192): act base4[kq][b][j] = pc[b][kq*128:+128] . aw1[.., j]
//   [192, 200): act tv[t][j] = ab1[j] + traj[t] . aw1[512:][:,j]
// ============================================================================
__global__ __launch_bounds__(512) void k4_soft(const int* __restrict__ np,
                                               const float* __restrict__ coords,
                                               const float* __restrict__ b2,
                                               const float* __restrict__ aw1,
                                               const float* __restrict__ ab1,
                                               const float* __restrict__ traj,
                                               float* __restrict__ out) {
    const int bid = blockIdx.x, tid = threadIdx.x;

    if (bid >= 128) {
        if (bid < 192) {
            // base partial: id = bid-128; b = id>>2, kq = id&3
            __shared__ float pc[128];
            const int id = bid - 128;
            const int b = id >> 2, kq = id & 3;
            if (tid < 128) {
                const int k = kq * 128 + tid;
                float m = -1e30f;
#pragma unroll
                for (int c = 0; c < NCHUNK5; c++)
                    m = fmaxf(m, g_pp[(b * NCHUNK5 + c) * HID + k]);
                pc[tid] = m;
            }
            __syncthreads();
            const int j = tid;
            float acc = 0.f;
            const float* wbase = aw1 + (size_t)(kq * 128) * HID + j;
#pragma unroll 4
            for (int k = 0; k < 128; k++) acc += pc[k] * wbase[(size_t)k * HID];
            g_base4[kq][b][j] = acc;
        } else {
            // tv: t = bid-192
            const int t = bid - 192, j = tid;
            float acc = ab1[j];
#pragma unroll 8
            for (int e = 0; e < EMB; e++)
                acc += traj[t * EMB + e] * aw1[(size_t)(HID + e) * HID + j];
            g_tv[t][j] = acc;
        }
        return;
    }

    const int b = bid >> 3, t = bid & 7;
    const int lane = tid & 31, warp = tid >> 5;
    int start = 0;
    for (int i = 0; i < b; i++) start += np[i];
    const int end = start + np[b];

    __shared__ float sred[16][4];
    __shared__ float mshared;

    // pass 1: max logit
    float m = -1e30f;
    for (int p = start + tid; p < end; p += 512) {
        float l = g_part[(size_t)p * 32 + t * 4]
                + g_part[((size_t)NPTS + p) * 32 + t * 4]
                + g_part[((size_t)2 * NPTS + p) * 32 + t * 4]
                + g_part[((size_t)3 * NPTS + p) * 32 + t * 4];
        m = fmaxf(m, l);
    }
#pragma unroll
    for (int o = 16; o > 0; o >>= 1) m = fmaxf(m, __shfl_down_sync(0xffffffffu, m, o));
    if (lane == 0) sred[warp][0] = m;
    __syncthreads();
    if (tid == 0) {
        float v = sred[0][0];
        for (int i = 1; i < 16; i++) v = fmaxf(v, sred[i][0]);
        mshared = v;
    }
    __syncthreads();
    const float mx = mshared;
    const float b2x = b2[1], b2y = b2[2], b2z = b2[3];

    // pass 2: exp-weighted sums
    float s = 0.f, sx = 0.f, sy = 0.f, sz = 0.f;
    for (int p = start + tid; p < end; p += 512) {
        float4 v0 = *(const float4*)(g_part + (size_t)p * 32 + t * 4);
        float4 v1 = *(const float4*)(g_part + ((size_t)NPTS + p) * 32 + t * 4);
        float4 v2 = *(const float4*)(g_part + ((size_t)2 * NPTS + p) * 32 + t * 4);
        float4 v3 = *(const float4*)(g_part + ((size_t)3 * NPTS + p) * 32 + t * 4);
        float l  = v0.x + v1.x + v2.x + v3.x;
        float dx = v0.y + v1.y + v2.y + v3.y;
        float dy = v0.z + v1.z + v2.z + v3.z;
        float dz = v0.w + v1.w + v2.w + v3.w;
        float e = expf(l - mx);
        s  += e;
        sx += e * (coords[p * 3 + 0] + dx + b2x);
        sy += e * (coords[p * 3 + 1] + dy + b2y);
        sz += e * (coords[p * 3 + 2] + dz + b2z);
    }
#pragma unroll
    for (int o = 16; o > 0; o >>= 1) {
        s  += __shfl_down_sync(0xffffffffu, s,  o);
        sx += __shfl_down_sync(0xffffffffu, sx, o);
        sy += __shfl_down_sync(0xffffffffu, sy, o);
        sz += __shfl_down_sync(0xffffffffu, sz, o);
    }
    if (lane == 0) { sred[warp][0] = s; sred[warp][1] = sx; sred[warp][2] = sy; sred[warp][3] = sz; }
    __syncthreads();
    if (tid == 0) {
        float ts = 0, tx = 0, ty = 0, tz = 0;
        for (int i = 0; i < 16; i++) { ts += sred[i][0]; tx += sred[i][1]; ty += sred[i][2]; tz += sred[i][3]; }
        float inv = 1.f / ts;
        out[(b * 8 + t) * 3 + 0] = tx * inv;
        out[(b * 8 + t) * 3 + 1] = ty * inv;
        out[(b * 8 + t) * 3 + 2] = tz * inv;
    }
}

// ============================================================================
// K6: act layer 2.  128 blocks (one per b,t), 512 thr.
//   hid = lrelu(sum base4 + tv); out = hid @ w2T + b2 (contiguous float4 k).
// ============================================================================
__global__ __launch_bounds__(512) void k6_act(const float* __restrict__ b2,
                                              float* __restrict__ out) {
    __shared__ float hid[HID];
    __shared__ float sred2[OUTC];
    const int bt = blockIdx.x;
    const int b = bt >> 3, t = bt & 7;
    const int tid = threadIdx.x;

    {
        float v = g_base4[0][b][tid] + g_base4[1][b][tid] +
                  g_base4[2][b][tid] + g_base4[3][b][tid] + g_tv[t][tid];
        hid[tid] = v >= 0.f ? v : 0.02f * v;
    }
    __syncthreads();

    const bool active = (tid < 2 * OUTC);
    const int h = active ? (tid >= OUTC ? 1 : 0) : 0;
    const int o = active ? (tid - h * OUTC) : 0;
    float a = 0.f;
    if (active) {
        const float* wrow = g_w2T + (size_t)o * HID + h * 256;
        const float* hrow = hid + h * 256;
#pragma unroll 8
        for (int k = 0; k < 256; k += 4) {
            float4 wv = *(const float4*)(wrow + k);
            a += hrow[k] * wv.x + hrow[k + 1] * wv.y +
                 hrow[k + 2] * wv.z + hrow[k + 3] * wv.w;
        }
        if (h) sred2[o] = a;
    }
    __syncthreads();
    if (active && !h) {
        float tot = a + sred2[o] + b2[o];
        const int XT = BATCH * TSTEPS * 3;
        const int XR = BATCH * TSTEPS * 216;
        if (o < 216)       out[XT + bt * 216 + o] = tot;
        else if (o == 216) out[XT + XR + bt] = tot;
        else               out[XT + XR + BATCH * TSTEPS + bt] = tot;
    }
}

// ============================================================================
extern "C" void kernel_launch(void* const* d_in, const int* in_sizes, int n_in,
                              void* d_out, int out_size) {
    const float* pe     = (const float*)d_in[0];
    const float* coords = (const float*)d_in[1];
    const float* traj   = (const float*)d_in[2];
    const float* hw1    = (const float*)d_in[3];
    const float* hb1    = (const float*)d_in[4];
    const float* hw2    = (const float*)d_in[5];
    const float* hb2    = (const float*)d_in[6];
    const float* aw1    = (const float*)d_in[7];
    const float* ab1    = (const float*)d_in[8];
    const float* aw2    = (const float*)d_in[9];
    const float* ab2    = (const float*)d_in[10];
    const int*   np     = (const int*)d_in[11];
    float* out = (float*)d_out;

    static bool attr_set = false;
    if (!attr_set) {
        cudaFuncSetAttribute(kgemm, cudaFuncAttributeMaxDynamicSharedMemorySize, SMEM_KG);
        attr_set = true;
    }

    kpre<<<4992, 256>>>(pe, hw1, hb1, traj, np, aw2);                // 1
    kgemm<<<dim3(NPTS / 256, 4), 512, SMEM_KG>>>(hw2);               // 2
    k4_soft<<<200, 512>>>(np, coords, hb2, aw1, ab1, traj, out);     // 3
    k6_act<<<BATCH * TSTEPS, 512>>>(ab2, out);                       // 4
}